// round 11
// baseline (speedup 1.0000x reference)
#include <cuda_runtime.h>
#include <cuda_fp16.h>
#include <cstdint>
#include <cstring>

#define NN 100000
#define EE 1000000
#define DD 128
#define BN_EPS 1e-5f

#define SCAN_B 256
#define SCAN_G ((NN + SCAN_B - 1) / SCAN_B)   // 391

// W interleaved layout (uint32 words): [layer][chunk(4)][kp(16)][n(128)][{hi,lo}]
#define WB_CHUNK_W (16 * 128 * 2)             // 4096 words per chunk
#define WB_LAYER_W (4 * WB_CHUNK_W)           // 16384 words per layer

// ---------------- static device scratch (no allocation allowed) ----------------
__device__ int      g_cnt_src[NN];
__device__ int      g_cnt_dst[NN];
__device__ int      g_fill[NN];
__device__ int      g_row_ptr[NN + 1];
__device__ int      g_csr_src[EE];
__device__ int      g_part[SCAN_G];
__device__ int      g_partoff[SCAN_G];
__device__ float    g_norm_src[NN];
__device__ float    g_norm_dst[NN];
__device__ uint32_t g_h_h[(NN + 128) * (DD / 2)];   // inter-layer h (half2), padded
__device__ uint32_t g_hs_h[NN * (DD / 2)];          // GEMM out hs (half2)
__device__ uint32_t g_w[3 * WB_LAYER_W];            // interleaved hi/lo fp16x2 W

// ---------------- helpers ----------------
__device__ __forceinline__ uint32_t h2_to_u32(__half2 h) {
    uint32_t u; memcpy(&u, &h, 4); return u;
}
__device__ __forceinline__ __half2 u32_to_h2(uint32_t u) {
    __half2 h; memcpy(&h, &u, 4); return h;
}

__device__ __forceinline__ void split2(float a, float b, uint32_t& hi, uint32_t& lo) {
    __half ha = __float2half_rn(a), hb = __float2half_rn(b);
    float ra = a - __half2float(ha), rb = b - __half2float(hb);
    __half la = __float2half_rn(ra), lb = __float2half_rn(rb);
    hi = ((uint32_t)__half_as_ushort(hb) << 16) | (uint32_t)__half_as_ushort(ha);
    lo = ((uint32_t)__half_as_ushort(lb) << 16) | (uint32_t)__half_as_ushort(la);
}

__device__ __forceinline__ void mma_f16(float* c, const uint32_t* a, const uint32_t* b) {
    asm volatile(
        "mma.sync.aligned.m16n8k16.row.col.f32.f16.f16.f32 "
        "{%0,%1,%2,%3}, {%4,%5,%6,%7}, {%8,%9}, {%0,%1,%2,%3};"
        : "+f"(c[0]), "+f"(c[1]), "+f"(c[2]), "+f"(c[3])
        : "r"(a[0]), "r"(a[1]), "r"(a[2]), "r"(a[3]), "r"(b[0]), "r"(b[1]));
}

#define CP_ASYNC16(saddr, gptr) \
    asm volatile("cp.async.cg.shared.global [%0], [%1], 16;" :: "r"(saddr), "l"(gptr))
#define CP_COMMIT() asm volatile("cp.async.commit_group;" ::: "memory")
#define CP_WAIT0()  asm volatile("cp.async.wait_group 0;" ::: "memory")

// ---------------- init: zero counters + prep all 3 W layers (interleaved) ----------------
__global__ void __launch_bounds__(256) k_init(const float* __restrict__ W0,
                                              const float* __restrict__ W1,
                                              const float* __restrict__ W2) {
    int i = blockIdx.x * blockDim.x + threadIdx.x;
    if (i < NN) { g_cnt_src[i] = 0; g_cnt_dst[i] = 0; g_fill[i] = 0; }
    if (i < 3 * 8192) {
        int layer = i >> 13;
        int idx = i & 8191;
        const float* W = (layer == 0) ? W0 : (layer == 1) ? W1 : W2;
        int kp = idx >> 7;       // 0..63
        int n = idx & 127;
        float w0 = W[(2 * kp) * DD + n];
        float w1 = W[(2 * kp + 1) * DD + n];
        uint32_t hi, lo;
        split2(w0, w1, hi, lo);
        int chunk = kp >> 4, kpin = kp & 15;
        int dst = layer * WB_LAYER_W + chunk * WB_CHUNK_W + kpin * 256 + n * 2;
        *(uint2*)(g_w + dst) = make_uint2(hi, lo);
    }
}

// ---------------- graph preprocessing ----------------
__global__ void k_degree(const int* __restrict__ src, const int* __restrict__ dst) {
    int e = blockIdx.x * blockDim.x + threadIdx.x;
    if (e < EE) {
        atomicAdd(&g_cnt_src[src[e]], 1);
        atomicAdd(&g_cnt_dst[dst[e]], 1);
    }
}

__global__ void k_norm() {
    int i = blockIdx.x * blockDim.x + threadIdx.x;
    if (i < NN) {
        g_norm_src[i] = rsqrtf((float)max(g_cnt_src[i], 1));
        g_norm_dst[i] = rsqrtf((float)max(g_cnt_dst[i], 1));
    }
}

__global__ void __launch_bounds__(SCAN_B) k_scan_part() {
    __shared__ int s[SCAN_B];
    int t = threadIdx.x;
    int i = blockIdx.x * SCAN_B + t;
    s[t] = (i < NN) ? g_cnt_dst[i] : 0;
    __syncthreads();
    for (int off = SCAN_B / 2; off > 0; off >>= 1) {
        if (t < off) s[t] += s[t + off];
        __syncthreads();
    }
    if (t == 0) g_part[blockIdx.x] = s[0];
}

__global__ void __launch_bounds__(512) k_scan_top() {
    __shared__ int s[512];
    int t = threadIdx.x;
    int v = (t < SCAN_G) ? g_part[t] : 0;
    s[t] = v;
    __syncthreads();
    for (int off = 1; off < 512; off <<= 1) {
        int u = (t >= off) ? s[t - off] : 0;
        __syncthreads();
        s[t] += u;
        __syncthreads();
    }
    if (t < SCAN_G) g_partoff[t] = s[t] - v;
    if (t == 511) g_row_ptr[NN] = s[511];
}

__global__ void __launch_bounds__(SCAN_B) k_scan_write() {
    __shared__ int s[SCAN_B];
    int t = threadIdx.x;
    int i = blockIdx.x * SCAN_B + t;
    int v = (i < NN) ? g_cnt_dst[i] : 0;
    s[t] = v;
    __syncthreads();
    for (int off = 1; off < SCAN_B; off <<= 1) {
        int u = (t >= off) ? s[t - off] : 0;
        __syncthreads();
        s[t] += u;
        __syncthreads();
    }
    if (i < NN) g_row_ptr[i] = g_partoff[blockIdx.x] + s[t] - v;
}

__global__ void k_fill(const int* __restrict__ src, const int* __restrict__ dst) {
    int e = blockIdx.x * blockDim.x + threadIdx.x;
    if (e < EE) {
        int d = dst[e];
        int pos = g_row_ptr[d] + atomicAdd(&g_fill[d], 1);
        g_csr_src[pos] = src[e];
    }
}

// ---------------- mma.sync GEMM: g_hs_h = half2(A @ W) ----------------
// aHalf=0: A = fp32 ext (x) scaled by norm_src; 3-term; A smem interleaved stride 40
// aHalf=1: A = g_h_h fp16; 2-term; A smem plain stride 20
#define A_ST32 40
#define A_ST16 20
#define A_STAGE_W 5120                          // 128 * 40
#define B_ROWSTRIDE 264                         // 128*2 + 8 pad (≡8 mod 32)
#define B_STAGE_W (16 * B_ROWSTRIDE)            // 4224
#define SM_A(s)   ((s) * A_STAGE_W)
#define SM_B(s)   (2 * A_STAGE_W + (s) * B_STAGE_W)
#define SM_WORDS  (2 * A_STAGE_W + 2 * B_STAGE_W)   // 18688
#define SM_BYTES  (SM_WORDS * 4)                     // 74752

__global__ void __launch_bounds__(256)
k_gemm_mma(const float* __restrict__ Aext, int aHalf, int layer) {
    extern __shared__ uint32_t sm[];
    uint32_t sm_base = (uint32_t)__cvta_generic_to_shared(sm);
    int tid = threadIdx.x;
    int lane = tid & 31;
    int wid = tid >> 5;
    int row0 = blockIdx.x * 128;
    int m0 = (wid & 3) * 32;
    int n0 = (wid >> 2) * 64;
    int r = lane >> 2;
    int cq = lane & 3;

    const uint32_t* Bg = g_w + layer * WB_LAYER_W;

    float acc[2][8][4];
#pragma unroll
    for (int mi = 0; mi < 2; mi++)
#pragma unroll
        for (int ni = 0; ni < 8; ni++)
#pragma unroll
            for (int q = 0; q < 4; q++) acc[mi][ni][q] = 0.f;

    // fp32-A bookkeeping
    int arow[4], ak4[4];
    float anm[4];
    float4 av[4];
    if (!aHalf) {
#pragma unroll
        for (int q = 0; q < 4; q++) {
            int fi = tid + q * 256;
            arow[q] = fi >> 3;
            ak4[q] = fi & 7;
            int grow = row0 + arow[q];
            anm[q] = (grow < NN) ? g_norm_src[grow] : 0.f;
            av[q] = (grow < NN) ? *(const float4*)(Aext + (size_t)grow * DD + ak4[q] * 4)
                                : make_float4(0.f, 0.f, 0.f, 0.f);
        }
    } else {
        // prologue A(0) cp.async: 512 x 16B
#pragma unroll
        for (int q = 0; q < 2; q++) {
            int fi = tid + q * 256;
            int row = fi >> 2;
            int q4 = fi & 3;
            const uint32_t* src = g_h_h + (size_t)(row0 + row) * 64 + q4 * 4;
            CP_ASYNC16(sm_base + (SM_A(0) + row * A_ST16 + q4 * 4) * 4, src);
        }
    }
    // prologue B(0): 1024 x 16B (interleaved hi/lo)
#pragma unroll
    for (int q = 0; q < 4; q++) {
        int fi = tid + q * 256;
        int kp = fi >> 6;
        int qq = fi & 63;
        CP_ASYNC16(sm_base + (SM_B(0) + kp * B_ROWSTRIDE + qq * 4) * 4,
                   (const uint4*)Bg + fi);
    }
    CP_COMMIT();

    for (int ch = 0; ch < 4; ch++) {
        int st = ch & 1;
        if (!aHalf) {
#pragma unroll
            for (int q = 0; q < 4; q++) {
                float nm = anm[q];
                uint32_t h0, l0, h1, l1;
                split2(av[q].x * nm, av[q].y * nm, h0, l0);
                split2(av[q].z * nm, av[q].w * nm, h1, l1);
                // interleaved: [m][kp][{hi,lo}]: kpair ak4*2 -> words ak4*4..+3
                *(uint4*)(sm + SM_A(st) + arow[q] * A_ST32 + ak4[q] * 4) =
                    make_uint4(h0, l0, h1, l1);
            }
        }
        CP_WAIT0();
        __syncthreads();

        if (ch < 3) {
            int nst = st ^ 1;
            if (!aHalf) {
#pragma unroll
                for (int q = 0; q < 4; q++) {
                    int grow = row0 + arow[q];
                    av[q] = (grow < NN)
                        ? *(const float4*)(Aext + (size_t)grow * DD + (ch + 1) * 32 + ak4[q] * 4)
                        : make_float4(0.f, 0.f, 0.f, 0.f);
                }
            } else {
#pragma unroll
                for (int q = 0; q < 2; q++) {
                    int fi = tid + q * 256;
                    int row = fi >> 2;
                    int q4 = fi & 3;
                    const uint32_t* src = g_h_h + (size_t)(row0 + row) * 64 + (ch + 1) * 16 + q4 * 4;
                    CP_ASYNC16(sm_base + (SM_A(nst) + row * A_ST16 + q4 * 4) * 4, src);
                }
            }
            const uint4* bsrc = (const uint4*)(Bg + (ch + 1) * WB_CHUNK_W);
#pragma unroll
            for (int q = 0; q < 4; q++) {
                int fi = tid + q * 256;
                int kp = fi >> 6;
                int qq = fi & 63;
                CP_ASYNC16(sm_base + (SM_B(nst) + kp * B_ROWSTRIDE + qq * 4) * 4,
                           bsrc + fi);
            }
            CP_COMMIT();
        }

        const uint32_t* A0 = sm + SM_A(st);
        const uint32_t* B0 = sm + SM_B(st);
#pragma unroll
        for (int ks = 0; ks < 2; ks++) {
            uint32_t ah[2][4], al[2][4];
            if (!aHalf) {
#pragma unroll
                for (int mi = 0; mi < 2; mi++) {
                    int base = (m0 + mi * 16 + r) * A_ST32 + (ks * 8 + cq) * 2;
                    uint2 u0 = *(const uint2*)(A0 + base);
                    uint2 u1 = *(const uint2*)(A0 + base + 8 * A_ST32);
                    uint2 u2 = *(const uint2*)(A0 + base + 8);
                    uint2 u3 = *(const uint2*)(A0 + base + 8 * A_ST32 + 8);
                    ah[mi][0] = u0.x; ah[mi][1] = u1.x; ah[mi][2] = u2.x; ah[mi][3] = u3.x;
                    al[mi][0] = u0.y; al[mi][1] = u1.y; al[mi][2] = u2.y; al[mi][3] = u3.y;
                }
            } else {
#pragma unroll
                for (int mi = 0; mi < 2; mi++) {
                    int b0 = (m0 + mi * 16 + r) * A_ST16 + ks * 8 + cq;
                    int b1 = b0 + 8 * A_ST16;
                    ah[mi][0] = A0[b0];     ah[mi][1] = A0[b1];
                    ah[mi][2] = A0[b0 + 4]; ah[mi][3] = A0[b1 + 4];
                }
            }
#pragma unroll
            for (int ni = 0; ni < 8; ni++) {
                int col = n0 + ni * 8 + r;
                int w0 = (ks * 8 + cq) * B_ROWSTRIDE + col * 2;
                uint2 b0 = *(const uint2*)(B0 + w0);
                uint2 b1 = *(const uint2*)(B0 + w0 + 4 * B_ROWSTRIDE);
                uint32_t bhf[2] = { b0.x, b1.x };
                uint32_t blf[2] = { b0.y, b1.y };
#pragma unroll
                for (int mi = 0; mi < 2; mi++) {
                    mma_f16(acc[mi][ni], ah[mi], bhf);
                    mma_f16(acc[mi][ni], ah[mi], blf);
                    if (!aHalf) mma_f16(acc[mi][ni], al[mi], bhf);
                }
            }
        }
    }

    // epilogue: pack half2, write -> g_hs_h (row = 64 words)
#pragma unroll
    for (int mi = 0; mi < 2; mi++) {
        int rowA = row0 + m0 + mi * 16 + r;
        int rowB = rowA + 8;
#pragma unroll
        for (int ni = 0; ni < 8; ni++) {
            int wcol = (n0 + ni * 8 + cq * 2) >> 1;
            if (rowA < NN)
                g_hs_h[(size_t)rowA * 64 + wcol] =
                    h2_to_u32(__floats2half2_rn(acc[mi][ni][0], acc[mi][ni][1]));
            if (rowB < NN)
                g_hs_h[(size_t)rowB * 64 + wcol] =
                    h2_to_u32(__floats2half2_rn(acc[mi][ni][2], acc[mi][ni][3]));
        }
    }
}

// ---------------- aggregate (gather CSR, fp16 source, unroll x4) ----------------
__global__ void __launch_bounds__(256)
k_agg(float* __restrict__ outExt,
      const float* __restrict__ bias,
      const float* __restrict__ gamma, const float* __restrict__ beta,
      const float* __restrict__ mean, const float* __restrict__ var,
      int do_bn) {
    int warp = (blockIdx.x * blockDim.x + threadIdx.x) >> 5;
    int lane = threadIdx.x & 31;
    if (warp >= NN) return;

    int s0 = g_row_ptr[warp];
    int s1 = g_row_ptr[warp + 1];
    int wcol = lane * 2;
    const uint32_t* hs = g_hs_h;
    const int* csr = g_csr_src;

    float4 ac0 = make_float4(0.f, 0.f, 0.f, 0.f);
    float4 ac1 = make_float4(0.f, 0.f, 0.f, 0.f);
    float4 ac2 = make_float4(0.f, 0.f, 0.f, 0.f);
    float4 ac3 = make_float4(0.f, 0.f, 0.f, 0.f);
    int j = s0;
    for (; j + 3 < s1; j += 4) {
        int i0 = csr[j], i1 = csr[j + 1], i2 = csr[j + 2], i3 = csr[j + 3];
        uint2 v0 = *(const uint2*)(hs + (size_t)i0 * 64 + wcol);
        uint2 v1 = *(const uint2*)(hs + (size_t)i1 * 64 + wcol);
        uint2 v2 = *(const uint2*)(hs + (size_t)i2 * 64 + wcol);
        uint2 v3 = *(const uint2*)(hs + (size_t)i3 * 64 + wcol);
        float2 p, q;
        p = __half22float2(u32_to_h2(v0.x)); q = __half22float2(u32_to_h2(v0.y));
        ac0.x += p.x; ac0.y += p.y; ac0.z += q.x; ac0.w += q.y;
        p = __half22float2(u32_to_h2(v1.x)); q = __half22float2(u32_to_h2(v1.y));
        ac1.x += p.x; ac1.y += p.y; ac1.z += q.x; ac1.w += q.y;
        p = __half22float2(u32_to_h2(v2.x)); q = __half22float2(u32_to_h2(v2.y));
        ac2.x += p.x; ac2.y += p.y; ac2.z += q.x; ac2.w += q.y;
        p = __half22float2(u32_to_h2(v3.x)); q = __half22float2(u32_to_h2(v3.y));
        ac3.x += p.x; ac3.y += p.y; ac3.z += q.x; ac3.w += q.y;
    }
    for (; j < s1; j++) {
        int i0 = csr[j];
        uint2 v0 = *(const uint2*)(hs + (size_t)i0 * 64 + wcol);
        float2 p = __half22float2(u32_to_h2(v0.x));
        float2 q = __half22float2(u32_to_h2(v0.y));
        ac0.x += p.x; ac0.y += p.y; ac0.z += q.x; ac0.w += q.y;
    }
    ac0.x += ac1.x + ac2.x + ac3.x;
    ac0.y += ac1.y + ac2.y + ac3.y;
    ac0.z += ac1.z + ac2.z + ac3.z;
    ac0.w += ac1.w + ac2.w + ac3.w;

    int c = lane * 4;
    float nd = g_norm_dst[warp];
    float4 bb = *(const float4*)(bias + c);
    float4 rr;
    rr.x = ac0.x * nd + bb.x;
    rr.y = ac0.y * nd + bb.y;
    rr.z = ac0.z * nd + bb.z;
    rr.w = ac0.w * nd + bb.w;

    if (do_bn) {
        float4 g = *(const float4*)(gamma + c);
        float4 be = *(const float4*)(beta + c);
        float4 m = *(const float4*)(mean + c);
        float4 vv = *(const float4*)(var + c);
        float ns = g_norm_src[warp];
        rr.x = fmaxf((rr.x - m.x) * rsqrtf(vv.x + BN_EPS) * g.x + be.x, 0.f) * ns;
        rr.y = fmaxf((rr.y - m.y) * rsqrtf(vv.y + BN_EPS) * g.y + be.y, 0.f) * ns;
        rr.z = fmaxf((rr.z - m.z) * rsqrtf(vv.z + BN_EPS) * g.z + be.z, 0.f) * ns;
        rr.w = fmaxf((rr.w - m.w) * rsqrtf(vv.w + BN_EPS) * g.w + be.w, 0.f) * ns;
        uint2 o;
        o.x = h2_to_u32(__floats2half2_rn(rr.x, rr.y));
        o.y = h2_to_u32(__floats2half2_rn(rr.z, rr.w));
        *(uint2*)(g_h_h + (size_t)warp * 64 + wcol) = o;
    } else {
        *(float4*)(outExt + (size_t)warp * DD + c) = rr;
    }
}

// ---------------- launch ----------------
extern "C" void kernel_launch(void* const* d_in, const int* in_sizes, int n_in,
                              void* d_out, int out_size) {
    const float* x   = (const float*)d_in[0];
    const int* esrc  = (const int*)d_in[1];
    const int* edst  = (const int*)d_in[2];
    const float* W0  = (const float*)d_in[3];
    const float* b0  = (const float*)d_in[4];
    const float* W1  = (const float*)d_in[5];
    const float* b1  = (const float*)d_in[6];
    const float* W2  = (const float*)d_in[7];
    const float* b2  = (const float*)d_in[8];
    const float* g0  = (const float*)d_in[9];
    const float* be0 = (const float*)d_in[10];
    const float* m0  = (const float*)d_in[11];
    const float* v0  = (const float*)d_in[12];
    const float* g1  = (const float*)d_in[13];
    const float* be1 = (const float*)d_in[14];
    const float* m1  = (const float*)d_in[15];
    const float* v1  = (const float*)d_in[16];
    float* out = (float*)d_out;

    const int nblkN = (NN + 255) / 256;
    const int nblkE = (EE + 255) / 256;
    const int gemmBlocks = (NN + 127) / 128;       // 782
    const int aggBlocks = (NN * 32 + 255) / 256;

    cudaFuncSetAttribute(k_gemm_mma, cudaFuncAttributeMaxDynamicSharedMemorySize, SM_BYTES);

    // launch 0: init (zero counters + prep all W)
    k_init<<<nblkN, 256>>>(W0, W1, W2);
    // launch 1-2: degrees + norms
    k_degree<<<nblkE, 256>>>(esrc, edst);
    k_norm<<<nblkN, 256>>>();
    // launch 3: layer-0 GEMM  (profiled slot)
    k_gemm_mma<<<gemmBlocks, 256, SM_BYTES>>>(x, 0, 0);
    // launches 4-7: CSR build (independent of GEMM)
    k_scan_part<<<SCAN_G, SCAN_B>>>();
    k_scan_top<<<1, 512>>>();
    k_scan_write<<<SCAN_G, SCAN_B>>>();
    k_fill<<<nblkE, 256>>>(esrc, edst);
    // layer 0 aggregate
    k_agg<<<aggBlocks, 256>>>(nullptr, b0, g0, be0, m0, v0, 1);
    // layer 1
    k_gemm_mma<<<gemmBlocks, 256, SM_BYTES>>>(nullptr, 1, 1);
    k_agg<<<aggBlocks, 256>>>(nullptr, b1, g1, be1, m1, v1, 1);
    // layer 2 -> d_out
    k_gemm_mma<<<gemmBlocks, 256, SM_BYTES>>>(nullptr, 1, 2);
    k_agg<<<aggBlocks, 256>>>(out, b2, nullptr, nullptr, nullptr, nullptr, 0);
}

// round 12
// speedup vs baseline: 1.1391x; 1.1391x over previous
#include <cuda_runtime.h>
#include <cuda_fp16.h>
#include <cstdint>
#include <cstring>

#define NN 100000
#define EE 1000000
#define DD 128
#define BN_EPS 1e-5f

#define SCAN_B 256
#define SCAN_G ((NN + SCAN_B - 1) / SCAN_B)   // 391

// W interleaved layout (uint32 words): [layer][chunk(4)][kp(16)][n(128)][{hi,lo}]
#define WB_CHUNK_W (16 * 128 * 2)             // 4096 words per chunk
#define WB_LAYER_W (4 * WB_CHUNK_W)           // 16384 words per layer

// ---------------- static device scratch (no allocation allowed) ----------------
__device__ int      g_cnt_src[NN];
__device__ int      g_cnt_dst[NN];
__device__ int      g_fill[NN];
__device__ int      g_row_ptr[NN + 1];
__device__ int      g_csr_src[EE];
__device__ int      g_part[SCAN_G];
__device__ int      g_partoff[SCAN_G];
__device__ float    g_norm_src[NN];
__device__ float    g_norm_dst[NN];
__device__ uint32_t g_h_h[(NN + 128) * (DD / 2)];   // inter-layer h (half2), padded
__device__ uint32_t g_hs_h[NN * (DD / 2)];          // GEMM out hs (half2)
__device__ uint32_t g_w[3 * WB_LAYER_W];            // interleaved hi/lo fp16x2 W

// ---------------- helpers ----------------
__device__ __forceinline__ uint32_t h2_to_u32(__half2 h) {
    uint32_t u; memcpy(&u, &h, 4); return u;
}
__device__ __forceinline__ __half2 u32_to_h2(uint32_t u) {
    __half2 h; memcpy(&h, &u, 4); return h;
}

__device__ __forceinline__ void split2(float a, float b, uint32_t& hi, uint32_t& lo) {
    __half ha = __float2half_rn(a), hb = __float2half_rn(b);
    float ra = a - __half2float(ha), rb = b - __half2float(hb);
    __half la = __float2half_rn(ra), lb = __float2half_rn(rb);
    hi = ((uint32_t)__half_as_ushort(hb) << 16) | (uint32_t)__half_as_ushort(ha);
    lo = ((uint32_t)__half_as_ushort(lb) << 16) | (uint32_t)__half_as_ushort(la);
}

__device__ __forceinline__ void mma_f16(float* c, const uint32_t* a, const uint32_t* b) {
    asm volatile(
        "mma.sync.aligned.m16n8k16.row.col.f32.f16.f16.f32 "
        "{%0,%1,%2,%3}, {%4,%5,%6,%7}, {%8,%9}, {%0,%1,%2,%3};"
        : "+f"(c[0]), "+f"(c[1]), "+f"(c[2]), "+f"(c[3])
        : "r"(a[0]), "r"(a[1]), "r"(a[2]), "r"(a[3]), "r"(b[0]), "r"(b[1]));
}

#define CP_ASYNC16(saddr, gptr) \
    asm volatile("cp.async.cg.shared.global [%0], [%1], 16;" :: "r"(saddr), "l"(gptr))
#define CP_COMMIT() asm volatile("cp.async.commit_group;" ::: "memory")
#define CP_WAIT0()  asm volatile("cp.async.wait_group 0;" ::: "memory")

// ---------------- init: zero counters + prep all 3 W layers (interleaved) ----------------
__global__ void __launch_bounds__(256) k_init(const float* __restrict__ W0,
                                              const float* __restrict__ W1,
                                              const float* __restrict__ W2) {
    int i = blockIdx.x * blockDim.x + threadIdx.x;
    if (i < NN) { g_cnt_src[i] = 0; g_cnt_dst[i] = 0; g_fill[i] = 0; }
    if (i < 3 * 8192) {
        int layer = i >> 13;
        int idx = i & 8191;
        const float* W = (layer == 0) ? W0 : (layer == 1) ? W1 : W2;
        int kp = idx >> 7;       // 0..63
        int n = idx & 127;
        float w0 = W[(2 * kp) * DD + n];
        float w1 = W[(2 * kp + 1) * DD + n];
        uint32_t hi, lo;
        split2(w0, w1, hi, lo);
        int chunk = kp >> 4, kpin = kp & 15;
        int dst = layer * WB_LAYER_W + chunk * WB_CHUNK_W + kpin * 256 + n * 2;
        *(uint2*)(g_w + dst) = make_uint2(hi, lo);
    }
}

// ---------------- graph preprocessing ----------------
__global__ void k_degree(const int* __restrict__ src, const int* __restrict__ dst) {
    int e = blockIdx.x * blockDim.x + threadIdx.x;
    if (e < EE) {
        atomicAdd(&g_cnt_src[src[e]], 1);
        atomicAdd(&g_cnt_dst[dst[e]], 1);
    }
}

__global__ void k_norm() {
    int i = blockIdx.x * blockDim.x + threadIdx.x;
    if (i < NN) {
        g_norm_src[i] = rsqrtf((float)max(g_cnt_src[i], 1));
        g_norm_dst[i] = rsqrtf((float)max(g_cnt_dst[i], 1));
    }
}

__global__ void __launch_bounds__(SCAN_B) k_scan_part() {
    __shared__ int s[SCAN_B];
    int t = threadIdx.x;
    int i = blockIdx.x * SCAN_B + t;
    s[t] = (i < NN) ? g_cnt_dst[i] : 0;
    __syncthreads();
    for (int off = SCAN_B / 2; off > 0; off >>= 1) {
        if (t < off) s[t] += s[t + off];
        __syncthreads();
    }
    if (t == 0) g_part[blockIdx.x] = s[0];
}

__global__ void __launch_bounds__(512) k_scan_top() {
    __shared__ int s[512];
    int t = threadIdx.x;
    int v = (t < SCAN_G) ? g_part[t] : 0;
    s[t] = v;
    __syncthreads();
    for (int off = 1; off < 512; off <<= 1) {
        int u = (t >= off) ? s[t - off] : 0;
        __syncthreads();
        s[t] += u;
        __syncthreads();
    }
    if (t < SCAN_G) g_partoff[t] = s[t] - v;
    if (t == 511) g_row_ptr[NN] = s[511];
}

__global__ void __launch_bounds__(SCAN_B) k_scan_write() {
    __shared__ int s[SCAN_B];
    int t = threadIdx.x;
    int i = blockIdx.x * SCAN_B + t;
    int v = (i < NN) ? g_cnt_dst[i] : 0;
    s[t] = v;
    __syncthreads();
    for (int off = 1; off < SCAN_B; off <<= 1) {
        int u = (t >= off) ? s[t - off] : 0;
        __syncthreads();
        s[t] += u;
        __syncthreads();
    }
    if (i < NN) g_row_ptr[i] = g_partoff[blockIdx.x] + s[t] - v;
}

__global__ void k_fill(const int* __restrict__ src, const int* __restrict__ dst) {
    int e = blockIdx.x * blockDim.x + threadIdx.x;
    if (e < EE) {
        int d = dst[e];
        int pos = g_row_ptr[d] + atomicAdd(&g_fill[d], 1);
        g_csr_src[pos] = src[e];
    }
}

// ---------------- mma.sync GEMM: g_hs_h = half2(A @ W) ----------------
// aHalf=0: A = fp32 ext (x) scaled by norm_src; 3-term; A smem = separate hi/lo stride 20
// aHalf=1: A = g_h_h fp16; 2-term; uses A-hi array only
// B smem: interleaved [kp][n][{hi,lo}], row stride 264 words (LDS.64 conflict-free)
#define A_ST 20
#define A_STAGE_W (128 * A_ST)                  // 2560 words
#define SM_AH(s)  ((s) * A_STAGE_W)
#define SM_AL(s)  (2 * A_STAGE_W + (s) * A_STAGE_W)
#define B_ROWSTRIDE 264
#define B_STAGE_W (16 * B_ROWSTRIDE)            // 4224
#define SM_B(s)   (4 * A_STAGE_W + (s) * B_STAGE_W)
#define SM_WORDS  (4 * A_STAGE_W + 2 * B_STAGE_W)   // 18688
#define SM_BYTES  (SM_WORDS * 4)                     // 74752

__global__ void __launch_bounds__(256, 2)
k_gemm_mma(const float* __restrict__ Aext, int aHalf, int layer) {
    extern __shared__ uint32_t sm[];
    uint32_t sm_base = (uint32_t)__cvta_generic_to_shared(sm);
    int tid = threadIdx.x;
    int lane = tid & 31;
    int wid = tid >> 5;
    int row0 = blockIdx.x * 128;
    int m0 = (wid & 3) * 32;
    int n0 = (wid >> 2) * 64;
    int r = lane >> 2;
    int cq = lane & 3;

    const uint32_t* Bg = g_w + layer * WB_LAYER_W;

    float acc[2][8][4];
#pragma unroll
    for (int mi = 0; mi < 2; mi++)
#pragma unroll
        for (int ni = 0; ni < 8; ni++)
#pragma unroll
            for (int q = 0; q < 4; q++) acc[mi][ni][q] = 0.f;

    // fp32-A: thread's slots are (row = fi>>3, k-quad = fi&7), fi = tid + q*256
    float anm[4];
    float4 av[4];
    if (!aHalf) {
#pragma unroll
        for (int q = 0; q < 4; q++) {
            int fi = tid + q * 256;
            int grow = row0 + (fi >> 3);
            anm[q] = (grow < NN) ? g_norm_src[grow] : 0.f;
            av[q] = (grow < NN) ? *(const float4*)(Aext + (size_t)grow * DD + (fi & 7) * 4)
                                : make_float4(0.f, 0.f, 0.f, 0.f);
        }
    } else {
#pragma unroll
        for (int q = 0; q < 2; q++) {
            int fi = tid + q * 256;
            int row = fi >> 2;
            int q4 = fi & 3;
            const uint32_t* src = g_h_h + (size_t)(row0 + row) * 64 + q4 * 4;
            CP_ASYNC16(sm_base + (SM_AH(0) + row * A_ST + q4 * 4) * 4, src);
        }
    }
    // prologue B(0): 1024 x 16B (interleaved hi/lo)
#pragma unroll
    for (int q = 0; q < 4; q++) {
        int fi = tid + q * 256;
        CP_ASYNC16(sm_base + (SM_B(0) + (fi >> 6) * B_ROWSTRIDE + (fi & 63) * 4) * 4,
                   (const uint4*)Bg + fi);
    }
    CP_COMMIT();

    for (int ch = 0; ch < 4; ch++) {
        int st = ch & 1;
        if (!aHalf) {
#pragma unroll
            for (int q = 0; q < 4; q++) {
                int fi = tid + q * 256;
                float nm = anm[q];
                uint32_t h0, l0, h1, l1;
                split2(av[q].x * nm, av[q].y * nm, h0, l0);
                split2(av[q].z * nm, av[q].w * nm, h1, l1);
                int off = (fi >> 3) * A_ST + (fi & 7) * 2;
                *(uint2*)(sm + SM_AH(st) + off) = make_uint2(h0, h1);
                *(uint2*)(sm + SM_AL(st) + off) = make_uint2(l0, l1);
            }
        }
        CP_WAIT0();
        __syncthreads();

        if (ch < 3) {
            int nst = st ^ 1;
            if (!aHalf) {
#pragma unroll
                for (int q = 0; q < 4; q++) {
                    int fi = tid + q * 256;
                    int grow = row0 + (fi >> 3);
                    av[q] = (grow < NN)
                        ? *(const float4*)(Aext + (size_t)grow * DD + (ch + 1) * 32 + (fi & 7) * 4)
                        : make_float4(0.f, 0.f, 0.f, 0.f);
                }
            } else {
#pragma unroll
                for (int q = 0; q < 2; q++) {
                    int fi = tid + q * 256;
                    int row = fi >> 2;
                    int q4 = fi & 3;
                    const uint32_t* src = g_h_h + (size_t)(row0 + row) * 64 + (ch + 1) * 16 + q4 * 4;
                    CP_ASYNC16(sm_base + (SM_AH(nst) + row * A_ST + q4 * 4) * 4, src);
                }
            }
            const uint4* bsrc = (const uint4*)(Bg + (ch + 1) * WB_CHUNK_W);
#pragma unroll
            for (int q = 0; q < 4; q++) {
                int fi = tid + q * 256;
                CP_ASYNC16(sm_base + (SM_B(nst) + (fi >> 6) * B_ROWSTRIDE + (fi & 63) * 4) * 4,
                           bsrc + fi);
            }
            CP_COMMIT();
        }

        const uint32_t* AH = sm + SM_AH(st);
        const uint32_t* AL = sm + SM_AL(st);
        const uint32_t* B0 = sm + SM_B(st);
#pragma unroll
        for (int ks = 0; ks < 2; ks++) {
            uint32_t ah[2][4], al[2][4];
#pragma unroll
            for (int mi = 0; mi < 2; mi++) {
                int b0 = (m0 + mi * 16 + r) * A_ST + ks * 8 + cq;
                int b1 = b0 + 8 * A_ST;
                ah[mi][0] = AH[b0];     ah[mi][1] = AH[b1];
                ah[mi][2] = AH[b0 + 4]; ah[mi][3] = AH[b1 + 4];
                if (!aHalf) {
                    al[mi][0] = AL[b0];     al[mi][1] = AL[b1];
                    al[mi][2] = AL[b0 + 4]; al[mi][3] = AL[b1 + 4];
                }
            }
#pragma unroll
            for (int ni = 0; ni < 8; ni++) {
                int col = n0 + ni * 8 + r;
                int w0 = (ks * 8 + cq) * B_ROWSTRIDE + col * 2;
                uint2 bq0 = *(const uint2*)(B0 + w0);
                uint2 bq1 = *(const uint2*)(B0 + w0 + 4 * B_ROWSTRIDE);
                uint32_t bhf[2] = { bq0.x, bq1.x };
                uint32_t blf[2] = { bq0.y, bq1.y };
#pragma unroll
                for (int mi = 0; mi < 2; mi++) {
                    mma_f16(acc[mi][ni], ah[mi], bhf);
                    mma_f16(acc[mi][ni], ah[mi], blf);
                    if (!aHalf) mma_f16(acc[mi][ni], al[mi], bhf);
                }
            }
        }
    }

    // epilogue: pack half2, write -> g_hs_h (row = 64 words)
#pragma unroll
    for (int mi = 0; mi < 2; mi++) {
        int rowA = row0 + m0 + mi * 16 + r;
        int rowB = rowA + 8;
#pragma unroll
        for (int ni = 0; ni < 8; ni++) {
            int wcol = (n0 + ni * 8 + cq * 2) >> 1;
            if (rowA < NN)
                g_hs_h[(size_t)rowA * 64 + wcol] =
                    h2_to_u32(__floats2half2_rn(acc[mi][ni][0], acc[mi][ni][1]));
            if (rowB < NN)
                g_hs_h[(size_t)rowB * 64 + wcol] =
                    h2_to_u32(__floats2half2_rn(acc[mi][ni][2], acc[mi][ni][3]));
        }
    }
}

// ---------------- aggregate (gather CSR, fp16 source, unroll x4) ----------------
__global__ void __launch_bounds__(256)
k_agg(float* __restrict__ outExt,
      const float* __restrict__ bias,
      const float* __restrict__ gamma, const float* __restrict__ beta,
      const float* __restrict__ mean, const float* __restrict__ var,
      int do_bn) {
    int warp = (blockIdx.x * blockDim.x + threadIdx.x) >> 5;
    int lane = threadIdx.x & 31;
    if (warp >= NN) return;

    int s0 = g_row_ptr[warp];
    int s1 = g_row_ptr[warp + 1];
    int wcol = lane * 2;
    const uint32_t* hs = g_hs_h;
    const int* csr = g_csr_src;

    float4 ac0 = make_float4(0.f, 0.f, 0.f, 0.f);
    float4 ac1 = make_float4(0.f, 0.f, 0.f, 0.f);
    float4 ac2 = make_float4(0.f, 0.f, 0.f, 0.f);
    float4 ac3 = make_float4(0.f, 0.f, 0.f, 0.f);
    int j = s0;
    for (; j + 3 < s1; j += 4) {
        int i0 = csr[j], i1 = csr[j + 1], i2 = csr[j + 2], i3 = csr[j + 3];
        uint2 v0 = *(const uint2*)(hs + (size_t)i0 * 64 + wcol);
        uint2 v1 = *(const uint2*)(hs + (size_t)i1 * 64 + wcol);
        uint2 v2 = *(const uint2*)(hs + (size_t)i2 * 64 + wcol);
        uint2 v3 = *(const uint2*)(hs + (size_t)i3 * 64 + wcol);
        float2 p, q;
        p = __half22float2(u32_to_h2(v0.x)); q = __half22float2(u32_to_h2(v0.y));
        ac0.x += p.x; ac0.y += p.y; ac0.z += q.x; ac0.w += q.y;
        p = __half22float2(u32_to_h2(v1.x)); q = __half22float2(u32_to_h2(v1.y));
        ac1.x += p.x; ac1.y += p.y; ac1.z += q.x; ac1.w += q.y;
        p = __half22float2(u32_to_h2(v2.x)); q = __half22float2(u32_to_h2(v2.y));
        ac2.x += p.x; ac2.y += p.y; ac2.z += q.x; ac2.w += q.y;
        p = __half22float2(u32_to_h2(v3.x)); q = __half22float2(u32_to_h2(v3.y));
        ac3.x += p.x; ac3.y += p.y; ac3.z += q.x; ac3.w += q.y;
    }
    for (; j < s1; j++) {
        int i0 = csr[j];
        uint2 v0 = *(const uint2*)(hs + (size_t)i0 * 64 + wcol);
        float2 p = __half22float2(u32_to_h2(v0.x));
        float2 q = __half22float2(u32_to_h2(v0.y));
        ac0.x += p.x; ac0.y += p.y; ac0.z += q.x; ac0.w += q.y;
    }
    ac0.x += ac1.x + ac2.x + ac3.x;
    ac0.y += ac1.y + ac2.y + ac3.y;
    ac0.z += ac1.z + ac2.z + ac3.z;
    ac0.w += ac1.w + ac2.w + ac3.w;

    int c = lane * 4;
    float nd = g_norm_dst[warp];
    float4 bb = *(const float4*)(bias + c);
    float4 rr;
    rr.x = ac0.x * nd + bb.x;
    rr.y = ac0.y * nd + bb.y;
    rr.z = ac0.z * nd + bb.z;
    rr.w = ac0.w * nd + bb.w;

    if (do_bn) {
        float4 g = *(const float4*)(gamma + c);
        float4 be = *(const float4*)(beta + c);
        float4 m = *(const float4*)(mean + c);
        float4 vv = *(const float4*)(var + c);
        float ns = g_norm_src[warp];
        rr.x = fmaxf((rr.x - m.x) * rsqrtf(vv.x + BN_EPS) * g.x + be.x, 0.f) * ns;
        rr.y = fmaxf((rr.y - m.y) * rsqrtf(vv.y + BN_EPS) * g.y + be.y, 0.f) * ns;
        rr.z = fmaxf((rr.z - m.z) * rsqrtf(vv.z + BN_EPS) * g.z + be.z, 0.f) * ns;
        rr.w = fmaxf((rr.w - m.w) * rsqrtf(vv.w + BN_EPS) * g.w + be.w, 0.f) * ns;
        uint2 o;
        o.x = h2_to_u32(__floats2half2_rn(rr.x, rr.y));
        o.y = h2_to_u32(__floats2half2_rn(rr.z, rr.w));
        *(uint2*)(g_h_h + (size_t)warp * 64 + wcol) = o;
    } else {
        *(float4*)(outExt + (size_t)warp * DD + c) = rr;
    }
}

// ---------------- launch ----------------
extern "C" void kernel_launch(void* const* d_in, const int* in_sizes, int n_in,
                              void* d_out, int out_size) {
    const float* x   = (const float*)d_in[0];
    const int* esrc  = (const int*)d_in[1];
    const int* edst  = (const int*)d_in[2];
    const float* W0  = (const float*)d_in[3];
    const float* b0  = (const float*)d_in[4];
    const float* W1  = (const float*)d_in[5];
    const float* b1  = (const float*)d_in[6];
    const float* W2  = (const float*)d_in[7];
    const float* b2  = (const float*)d_in[8];
    const float* g0  = (const float*)d_in[9];
    const float* be0 = (const float*)d_in[10];
    const float* m0  = (const float*)d_in[11];
    const float* v0  = (const float*)d_in[12];
    const float* g1  = (const float*)d_in[13];
    const float* be1 = (const float*)d_in[14];
    const float* m1  = (const float*)d_in[15];
    const float* v1  = (const float*)d_in[16];
    float* out = (float*)d_out;

    const int nblkN = (NN + 255) / 256;
    const int nblkE = (EE + 255) / 256;
    const int gemmBlocks = (NN + 127) / 128;       // 782
    const int aggBlocks = (NN * 32 + 255) / 256;

    cudaFuncSetAttribute(k_gemm_mma, cudaFuncAttributeMaxDynamicSharedMemorySize, SM_BYTES);

    // launch 0: init (zero counters + prep all W)
    k_init<<<nblkN, 256>>>(W0, W1, W2);
    // launch 1-2: degrees + norms
    k_degree<<<nblkE, 256>>>(esrc, edst);
    k_norm<<<nblkN, 256>>>();
    // launch 3: layer-0 GEMM  (profiled slot)
    k_gemm_mma<<<gemmBlocks, 256, SM_BYTES>>>(x, 0, 0);
    // launches 4-7: CSR build (independent of GEMM)
    k_scan_part<<<SCAN_G, SCAN_B>>>();
    k_scan_top<<<1, 512>>>();
    k_scan_write<<<SCAN_G, SCAN_B>>>();
    k_fill<<<nblkE, 256>>>(esrc, edst);
    // layer 0 aggregate
    k_agg<<<aggBlocks, 256>>>(nullptr, b0, g0, be0, m0, v0, 1);
    // layer 1
    k_gemm_mma<<<gemmBlocks, 256, SM_BYTES>>>(nullptr, 1, 1);
    k_agg<<<aggBlocks, 256>>>(nullptr, b1, g1, be1, m1, v1, 1);
    // layer 2 -> d_out
    k_gemm_mma<<<gemmBlocks, 256, SM_BYTES>>>(nullptr, 1, 2);
    k_agg<<<aggBlocks, 256>>>(out, b2, nullptr, nullptr, nullptr, nullptr, 0);
}

// round 13
// speedup vs baseline: 1.1835x; 1.0390x over previous
#include <cuda_runtime.h>
#include <cuda_fp16.h>
#include <cstdint>
#include <cstring>

#define NN 100000
#define EE 1000000
#define DD 128
#define BN_EPS 1e-5f

#define SCAN_B 256
#define SCAN_G ((NN + SCAN_B - 1) / SCAN_B)   // 391

// W layout (uint32 k-pair words): [layer][chunk(4)][n(128)][kp(16)]  (k-major rows)
#define WB_CHUNK_W (128 * 16)                 // 2048 words per chunk
#define WB_LAYER_W (4 * WB_CHUNK_W)           // 8192 words per layer

// ---------------- static device scratch (no allocation allowed) ----------------
__device__ int      g_cnt_src[NN];
__device__ int      g_cnt_dst[NN];
__device__ int      g_fill[NN];
__device__ int      g_row_ptr[NN + 1];
__device__ int      g_csr_src[EE];
__device__ int      g_part[SCAN_G];
__device__ int      g_partoff[SCAN_G];
__device__ float    g_norm_src[NN];
__device__ float    g_norm_dst[NN];
__device__ uint32_t g_h_h[(NN + 128) * (DD / 2)];   // inter-layer h (half2), padded
__device__ uint32_t g_hs_h[NN * (DD / 2)];          // GEMM out hs (half2)
__device__ uint32_t g_w_hi[3 * WB_LAYER_W];
__device__ uint32_t g_w_lo[3 * WB_LAYER_W];

// ---------------- helpers ----------------
__device__ __forceinline__ uint32_t h2_to_u32(__half2 h) {
    uint32_t u; memcpy(&u, &h, 4); return u;
}
__device__ __forceinline__ __half2 u32_to_h2(uint32_t u) {
    __half2 h; memcpy(&h, &u, 4); return h;
}

__device__ __forceinline__ void split2(float a, float b, uint32_t& hi, uint32_t& lo) {
    __half ha = __float2half_rn(a), hb = __float2half_rn(b);
    float ra = a - __half2float(ha), rb = b - __half2float(hb);
    __half la = __float2half_rn(ra), lb = __float2half_rn(rb);
    hi = ((uint32_t)__half_as_ushort(hb) << 16) | (uint32_t)__half_as_ushort(ha);
    lo = ((uint32_t)__half_as_ushort(lb) << 16) | (uint32_t)__half_as_ushort(la);
}

__device__ __forceinline__ void mma_f16(float* c, const uint32_t* a, const uint32_t* b) {
    asm volatile(
        "mma.sync.aligned.m16n8k16.row.col.f32.f16.f16.f32 "
        "{%0,%1,%2,%3}, {%4,%5,%6,%7}, {%8,%9}, {%0,%1,%2,%3};"
        : "+f"(c[0]), "+f"(c[1]), "+f"(c[2]), "+f"(c[3])
        : "r"(a[0]), "r"(a[1]), "r"(a[2]), "r"(a[3]), "r"(b[0]), "r"(b[1]));
}

__device__ __forceinline__ void ldsm_x4(uint32_t& r0, uint32_t& r1, uint32_t& r2,
                                        uint32_t& r3, uint32_t saddr) {
    asm volatile("ldmatrix.sync.aligned.m8n8.x4.shared.b16 {%0,%1,%2,%3}, [%4];"
                 : "=r"(r0), "=r"(r1), "=r"(r2), "=r"(r3) : "r"(saddr));
}

#define CP_ASYNC16(saddr, gptr) \
    asm volatile("cp.async.cg.shared.global [%0], [%1], 16;" :: "r"(saddr), "l"(gptr))
#define CP_COMMIT() asm volatile("cp.async.commit_group;" ::: "memory")
#define CP_WAIT0()  asm volatile("cp.async.wait_group 0;" ::: "memory")

// ---------------- init: zero counters + prep all 3 W layers ----------------
// W prep: thread (layer, kp, n) packs W[2kp][n],W[2kp+1][n] -> word at [chunk][n][kp&15]
__global__ void __launch_bounds__(256) k_init(const float* __restrict__ W0,
                                              const float* __restrict__ W1,
                                              const float* __restrict__ W2) {
    int i = blockIdx.x * blockDim.x + threadIdx.x;
    if (i < NN) { g_cnt_src[i] = 0; g_cnt_dst[i] = 0; g_fill[i] = 0; }
    if (i < 3 * 8192) {
        int layer = i >> 13;
        int idx = i & 8191;
        const float* W = (layer == 0) ? W0 : (layer == 1) ? W1 : W2;
        int kp = idx >> 7;       // 0..63
        int n = idx & 127;
        float w0 = W[(2 * kp) * DD + n];
        float w1 = W[(2 * kp + 1) * DD + n];
        uint32_t hi, lo;
        split2(w0, w1, hi, lo);
        int dst = layer * WB_LAYER_W + (kp >> 4) * WB_CHUNK_W + n * 16 + (kp & 15);
        g_w_hi[dst] = hi;
        g_w_lo[dst] = lo;
    }
}

// ---------------- graph preprocessing ----------------
__global__ void k_degree(const int* __restrict__ src, const int* __restrict__ dst) {
    int e = blockIdx.x * blockDim.x + threadIdx.x;
    if (e < EE) {
        atomicAdd(&g_cnt_src[src[e]], 1);
        atomicAdd(&g_cnt_dst[dst[e]], 1);
    }
}

__global__ void k_norm() {
    int i = blockIdx.x * blockDim.x + threadIdx.x;
    if (i < NN) {
        g_norm_src[i] = rsqrtf((float)max(g_cnt_src[i], 1));
        g_norm_dst[i] = rsqrtf((float)max(g_cnt_dst[i], 1));
    }
}

__global__ void __launch_bounds__(SCAN_B) k_scan_part() {
    __shared__ int s[SCAN_B];
    int t = threadIdx.x;
    int i = blockIdx.x * SCAN_B + t;
    s[t] = (i < NN) ? g_cnt_dst[i] : 0;
    __syncthreads();
    for (int off = SCAN_B / 2; off > 0; off >>= 1) {
        if (t < off) s[t] += s[t + off];
        __syncthreads();
    }
    if (t == 0) g_part[blockIdx.x] = s[0];
}

__global__ void __launch_bounds__(512) k_scan_top() {
    __shared__ int s[512];
    int t = threadIdx.x;
    int v = (t < SCAN_G) ? g_part[t] : 0;
    s[t] = v;
    __syncthreads();
    for (int off = 1; off < 512; off <<= 1) {
        int u = (t >= off) ? s[t - off] : 0;
        __syncthreads();
        s[t] += u;
        __syncthreads();
    }
    if (t < SCAN_G) g_partoff[t] = s[t] - v;
    if (t == 511) g_row_ptr[NN] = s[511];
}

__global__ void __launch_bounds__(SCAN_B) k_scan_write() {
    __shared__ int s[SCAN_B];
    int t = threadIdx.x;
    int i = blockIdx.x * SCAN_B + t;
    int v = (i < NN) ? g_cnt_dst[i] : 0;
    s[t] = v;
    __syncthreads();
    for (int off = 1; off < SCAN_B; off <<= 1) {
        int u = (t >= off) ? s[t - off] : 0;
        __syncthreads();
        s[t] += u;
        __syncthreads();
    }
    if (i < NN) g_row_ptr[i] = g_partoff[blockIdx.x] + s[t] - v;
}

__global__ void k_fill(const int* __restrict__ src, const int* __restrict__ dst) {
    int e = blockIdx.x * blockDim.x + threadIdx.x;
    if (e < EE) {
        int d = dst[e];
        int pos = g_row_ptr[d] + atomicAdd(&g_fill[d], 1);
        g_csr_src[pos] = src[e];
    }
}

// ---------------- mma.sync GEMM: g_hs_h = half2(A @ W) ----------------
// A smem: [m][kp] stride 20 words, separate hi/lo (scalar LDS, R10-proven).
// B smem: [n][kp] stride 20 words (k-major rows), separate hi/lo, via ldmatrix.x4.
#define A_ST 20
#define STAGE_W (128 * A_ST)                    // 2560 words
#define SM_AH(s)  ((s) * STAGE_W)
#define SM_AL(s)  (2 * STAGE_W + (s) * STAGE_W)
#define SM_BH(s)  (4 * STAGE_W + (s) * STAGE_W)
#define SM_BL(s)  (6 * STAGE_W + (s) * STAGE_W)
#define SM_WORDS  (8 * STAGE_W)                 // 20480
#define SM_BYTES  (SM_WORDS * 4)                // 81920

__global__ void __launch_bounds__(256, 2)
k_gemm_mma(const float* __restrict__ Aext, int aHalf, int layer) {
    extern __shared__ uint32_t sm[];
    uint32_t sm_base = (uint32_t)__cvta_generic_to_shared(sm);
    int tid = threadIdx.x;
    int lane = tid & 31;
    int wid = tid >> 5;
    int row0 = blockIdx.x * 128;
    int m0 = (wid & 3) * 32;
    int n0 = (wid >> 2) * 64;
    int r = lane >> 2;
    int cq = lane & 3;
    // ldsm lane mapping: group g = lane>>3 selects matrix, rl = lane&7 its row
    int g4 = lane >> 3;
    int rl = lane & 7;

    const uint32_t* BHg = g_w_hi + layer * WB_LAYER_W;
    const uint32_t* BLg = g_w_lo + layer * WB_LAYER_W;

    float acc[2][8][4];
#pragma unroll
    for (int mi = 0; mi < 2; mi++)
#pragma unroll
        for (int ni = 0; ni < 8; ni++)
#pragma unroll
            for (int q = 0; q < 4; q++) acc[mi][ni][q] = 0.f;

    // fp32-A: thread slots (row = fi>>3, k-quad = fi&7), fi = tid + q*256
    float anm[4];
    float4 av[4];
    if (!aHalf) {
#pragma unroll
        for (int q = 0; q < 4; q++) {
            int fi = tid + q * 256;
            int grow = row0 + (fi >> 3);
            anm[q] = (grow < NN) ? g_norm_src[grow] : 0.f;
            av[q] = (grow < NN) ? *(const float4*)(Aext + (size_t)grow * DD + (fi & 7) * 4)
                                : make_float4(0.f, 0.f, 0.f, 0.f);
        }
    } else {
#pragma unroll
        for (int q = 0; q < 2; q++) {
            int fi = tid + q * 256;
            int row = fi >> 2;
            int q4 = fi & 3;
            const uint32_t* src = g_h_h + (size_t)(row0 + row) * 64 + q4 * 4;
            CP_ASYNC16(sm_base + (SM_AH(0) + row * A_ST + q4 * 4) * 4, src);
        }
    }
    // prologue B(0): 512 x 16B per array (rows of 16 words -> 4 quads)
#pragma unroll
    for (int q = 0; q < 2; q++) {
        int fi = tid + q * 256;
        int row = fi >> 2;
        int q4 = fi & 3;
        uint32_t doff = (row * A_ST + q4 * 4) * 4;
        CP_ASYNC16(sm_base + SM_BH(0) * 4 + doff, (const uint4*)BHg + fi);
        CP_ASYNC16(sm_base + SM_BL(0) * 4 + doff, (const uint4*)BLg + fi);
    }
    CP_COMMIT();

    for (int ch = 0; ch < 4; ch++) {
        int st = ch & 1;
        if (!aHalf) {
#pragma unroll
            for (int q = 0; q < 4; q++) {
                int fi = tid + q * 256;
                float nm = anm[q];
                uint32_t h0, l0, h1, l1;
                split2(av[q].x * nm, av[q].y * nm, h0, l0);
                split2(av[q].z * nm, av[q].w * nm, h1, l1);
                int off = (fi >> 3) * A_ST + (fi & 7) * 2;
                *(uint2*)(sm + SM_AH(st) + off) = make_uint2(h0, h1);
                *(uint2*)(sm + SM_AL(st) + off) = make_uint2(l0, l1);
            }
        }
        CP_WAIT0();
        __syncthreads();

        if (ch < 3) {
            int nst = st ^ 1;
            if (!aHalf) {
#pragma unroll
                for (int q = 0; q < 4; q++) {
                    int fi = tid + q * 256;
                    int grow = row0 + (fi >> 3);
                    av[q] = (grow < NN)
                        ? *(const float4*)(Aext + (size_t)grow * DD + (ch + 1) * 32 + (fi & 7) * 4)
                        : make_float4(0.f, 0.f, 0.f, 0.f);
                }
            } else {
#pragma unroll
                for (int q = 0; q < 2; q++) {
                    int fi = tid + q * 256;
                    int row = fi >> 2;
                    int q4 = fi & 3;
                    const uint32_t* src = g_h_h + (size_t)(row0 + row) * 64 + (ch + 1) * 16 + q4 * 4;
                    CP_ASYNC16(sm_base + (SM_AH(nst) + row * A_ST + q4 * 4) * 4, src);
                }
            }
#pragma unroll
            for (int q = 0; q < 2; q++) {
                int fi = tid + q * 256;
                int row = fi >> 2;
                int q4 = fi & 3;
                uint32_t doff = (row * A_ST + q4 * 4) * 4;
                CP_ASYNC16(sm_base + SM_BH(nst) * 4 + doff,
                           (const uint4*)(BHg + (ch + 1) * WB_CHUNK_W) + fi);
                CP_ASYNC16(sm_base + SM_BL(nst) * 4 + doff,
                           (const uint4*)(BLg + (ch + 1) * WB_CHUNK_W) + fi);
            }
            CP_COMMIT();
        }

        const uint32_t* AH = sm + SM_AH(st);
        const uint32_t* AL = sm + SM_AL(st);
        uint32_t bh_base = sm_base + SM_BH(st) * 4;
        uint32_t bl_base = sm_base + SM_BL(st) * 4;
#pragma unroll
        for (int ks = 0; ks < 2; ks++) {
            uint32_t ah[2][4], al[2][4];
#pragma unroll
            for (int mi = 0; mi < 2; mi++) {
                int b0 = (m0 + mi * 16 + r) * A_ST + ks * 8 + cq;
                int b1 = b0 + 8 * A_ST;
                ah[mi][0] = AH[b0];     ah[mi][1] = AH[b1];
                ah[mi][2] = AH[b0 + 4]; ah[mi][3] = AH[b1 + 4];
                if (!aHalf) {
                    al[mi][0] = AL[b0];     al[mi][1] = AL[b1];
                    al[mi][2] = AL[b0 + 4]; al[mi][3] = AL[b1 + 4];
                }
            }
#pragma unroll
            for (int ni2 = 0; ni2 < 4; ni2++) {
                // ldsm x4: matrices (n-block, k-half): g4 = {ni2*2 n0-7 k0, k8, ni2*2+1 k0, k8}
                int nrow = n0 + ni2 * 16 + (g4 >> 1) * 8 + rl;
                uint32_t koff = (uint32_t)(ks * 8 + (g4 & 1) * 4) * 4;  // bytes
                uint32_t maddr = (uint32_t)(nrow * A_ST) * 4 + koff;
                uint32_t bh0, bh1, bh2, bh3, bl0, bl1, bl2, bl3;
                ldsm_x4(bh0, bh1, bh2, bh3, bh_base + maddr);
                ldsm_x4(bl0, bl1, bl2, bl3, bl_base + maddr);
                uint32_t bhfA[2] = { bh0, bh1 }, blfA[2] = { bl0, bl1 };
                uint32_t bhfB[2] = { bh2, bh3 }, blfB[2] = { bl2, bl3 };
#pragma unroll
                for (int mi = 0; mi < 2; mi++) {
                    mma_f16(acc[mi][ni2 * 2], ah[mi], bhfA);
                    mma_f16(acc[mi][ni2 * 2], ah[mi], blfA);
                    if (!aHalf) mma_f16(acc[mi][ni2 * 2], al[mi], bhfA);
                    mma_f16(acc[mi][ni2 * 2 + 1], ah[mi], bhfB);
                    mma_f16(acc[mi][ni2 * 2 + 1], ah[mi], blfB);
                    if (!aHalf) mma_f16(acc[mi][ni2 * 2 + 1], al[mi], bhfB);
                }
            }
        }
    }

    // epilogue: pack half2, write -> g_hs_h (row = 64 words)
#pragma unroll
    for (int mi = 0; mi < 2; mi++) {
        int rowA = row0 + m0 + mi * 16 + r;
        int rowB = rowA + 8;
#pragma unroll
        for (int ni = 0; ni < 8; ni++) {
            int wcol = (n0 + ni * 8 + cq * 2) >> 1;
            if (rowA < NN)
                g_hs_h[(size_t)rowA * 64 + wcol] =
                    h2_to_u32(__floats2half2_rn(acc[mi][ni][0], acc[mi][ni][1]));
            if (rowB < NN)
                g_hs_h[(size_t)rowB * 64 + wcol] =
                    h2_to_u32(__floats2half2_rn(acc[mi][ni][2], acc[mi][ni][3]));
        }
    }
}

// ---------------- aggregate (gather CSR, fp16 source, unroll x4) ----------------
__global__ void __launch_bounds__(256)
k_agg(float* __restrict__ outExt,
      const float* __restrict__ bias,
      const float* __restrict__ gamma, const float* __restrict__ beta,
      const float* __restrict__ mean, const float* __restrict__ var,
      int do_bn) {
    int warp = (blockIdx.x * blockDim.x + threadIdx.x) >> 5;
    int lane = threadIdx.x & 31;
    if (warp >= NN) return;

    int s0 = g_row_ptr[warp];
    int s1 = g_row_ptr[warp + 1];
    int wcol = lane * 2;
    const uint32_t* hs = g_hs_h;
    const int* csr = g_csr_src;

    float4 ac0 = make_float4(0.f, 0.f, 0.f, 0.f);
    float4 ac1 = make_float4(0.f, 0.f, 0.f, 0.f);
    float4 ac2 = make_float4(0.f, 0.f, 0.f, 0.f);
    float4 ac3 = make_float4(0.f, 0.f, 0.f, 0.f);
    int j = s0;
    for (; j + 3 < s1; j += 4) {
        int i0 = csr[j], i1 = csr[j + 1], i2 = csr[j + 2], i3 = csr[j + 3];
        uint2 v0 = *(const uint2*)(hs + (size_t)i0 * 64 + wcol);
        uint2 v1 = *(const uint2*)(hs + (size_t)i1 * 64 + wcol);
        uint2 v2 = *(const uint2*)(hs + (size_t)i2 * 64 + wcol);
        uint2 v3 = *(const uint2*)(hs + (size_t)i3 * 64 + wcol);
        float2 p, q;
        p = __half22float2(u32_to_h2(v0.x)); q = __half22float2(u32_to_h2(v0.y));
        ac0.x += p.x; ac0.y += p.y; ac0.z += q.x; ac0.w += q.y;
        p = __half22float2(u32_to_h2(v1.x)); q = __half22float2(u32_to_h2(v1.y));
        ac1.x += p.x; ac1.y += p.y; ac1.z += q.x; ac1.w += q.y;
        p = __half22float2(u32_to_h2(v2.x)); q = __half22float2(u32_to_h2(v2.y));
        ac2.x += p.x; ac2.y += p.y; ac2.z += q.x; ac2.w += q.y;
        p = __half22float2(u32_to_h2(v3.x)); q = __half22float2(u32_to_h2(v3.y));
        ac3.x += p.x; ac3.y += p.y; ac3.z += q.x; ac3.w += q.y;
    }
    for (; j < s1; j++) {
        int i0 = csr[j];
        uint2 v0 = *(const uint2*)(hs + (size_t)i0 * 64 + wcol);
        float2 p = __half22float2(u32_to_h2(v0.x));
        float2 q = __half22float2(u32_to_h2(v0.y));
        ac0.x += p.x; ac0.y += p.y; ac0.z += q.x; ac0.w += q.y;
    }
    ac0.x += ac1.x + ac2.x + ac3.x;
    ac0.y += ac1.y + ac2.y + ac3.y;
    ac0.z += ac1.z + ac2.z + ac3.z;
    ac0.w += ac1.w + ac2.w + ac3.w;

    int c = lane * 4;
    float nd = g_norm_dst[warp];
    float4 bb = *(const float4*)(bias + c);
    float4 rr;
    rr.x = ac0.x * nd + bb.x;
    rr.y = ac0.y * nd + bb.y;
    rr.z = ac0.z * nd + bb.z;
    rr.w = ac0.w * nd + bb.w;

    if (do_bn) {
        float4 g = *(const float4*)(gamma + c);
        float4 be = *(const float4*)(beta + c);
        float4 m = *(const float4*)(mean + c);
        float4 vv = *(const float4*)(var + c);
        float ns = g_norm_src[warp];
        rr.x = fmaxf((rr.x - m.x) * rsqrtf(vv.x + BN_EPS) * g.x + be.x, 0.f) * ns;
        rr.y = fmaxf((rr.y - m.y) * rsqrtf(vv.y + BN_EPS) * g.y + be.y, 0.f) * ns;
        rr.z = fmaxf((rr.z - m.z) * rsqrtf(vv.z + BN_EPS) * g.z + be.z, 0.f) * ns;
        rr.w = fmaxf((rr.w - m.w) * rsqrtf(vv.w + BN_EPS) * g.w + be.w, 0.f) * ns;
        uint2 o;
        o.x = h2_to_u32(__floats2half2_rn(rr.x, rr.y));
        o.y = h2_to_u32(__floats2half2_rn(rr.z, rr.w));
        *(uint2*)(g_h_h + (size_t)warp * 64 + wcol) = o;
    } else {
        *(float4*)(outExt + (size_t)warp * DD + c) = rr;
    }
}

// ---------------- launch ----------------
extern "C" void kernel_launch(void* const* d_in, const int* in_sizes, int n_in,
                              void* d_out, int out_size) {
    const float* x   = (const float*)d_in[0];
    const int* esrc  = (const int*)d_in[1];
    const int* edst  = (const int*)d_in[2];
    const float* W0  = (const float*)d_in[3];
    const float* b0  = (const float*)d_in[4];
    const float* W1  = (const float*)d_in[5];
    const float* b1  = (const float*)d_in[6];
    const float* W2  = (const float*)d_in[7];
    const float* b2  = (const float*)d_in[8];
    const float* g0  = (const float*)d_in[9];
    const float* be0 = (const float*)d_in[10];
    const float* m0  = (const float*)d_in[11];
    const float* v0  = (const float*)d_in[12];
    const float* g1  = (const float*)d_in[13];
    const float* be1 = (const float*)d_in[14];
    const float* m1  = (const float*)d_in[15];
    const float* v1  = (const float*)d_in[16];
    float* out = (float*)d_out;

    const int nblkN = (NN + 255) / 256;
    const int nblkE = (EE + 255) / 256;
    const int gemmBlocks = (NN + 127) / 128;       // 782
    const int aggBlocks = (NN * 32 + 255) / 256;

    cudaFuncSetAttribute(k_gemm_mma, cudaFuncAttributeMaxDynamicSharedMemorySize, SM_BYTES);

    // launch 0: init (zero counters + prep all W)
    k_init<<<nblkN, 256>>>(W0, W1, W2);
    // launch 1-2: degrees + norms
    k_degree<<<nblkE, 256>>>(esrc, edst);
    k_norm<<<nblkN, 256>>>();
    // launch 3: layer-0 GEMM  (profiled slot)
    k_gemm_mma<<<gemmBlocks, 256, SM_BYTES>>>(x, 0, 0);
    // launches 4-7: CSR build (independent of GEMM)
    k_scan_part<<<SCAN_G, SCAN_B>>>();
    k_scan_top<<<1, 512>>>();
    k_scan_write<<<SCAN_G, SCAN_B>>>();
    k_fill<<<nblkE, 256>>>(esrc, edst);
    // layer 0 aggregate
    k_agg<<<aggBlocks, 256>>>(nullptr, b0, g0, be0, m0, v0, 1);
    // layer 1
    k_gemm_mma<<<gemmBlocks, 256, SM_BYTES>>>(nullptr, 1, 1);
    k_agg<<<aggBlocks, 256>>>(nullptr, b1, g1, be1, m1, v1, 1);
    // layer 2 -> d_out
    k_gemm_mma<<<gemmBlocks, 256, SM_BYTES>>>(nullptr, 1, 2);
    k_agg<<<aggBlocks, 256>>>(out, b2, nullptr, nullptr, nullptr, nullptr, 0);
}

// round 16
// speedup vs baseline: 1.1862x; 1.0023x over previous
#include <cuda_runtime.h>
#include <cuda_fp16.h>
#include <cstdint>
#include <cstring>

#define NN 100000
#define EE 1000000
#define DD 128
#define BN_EPS 1e-5f

#define SCAN_B 256
#define SCAN_G ((NN + SCAN_B - 1) / SCAN_B)   // 391

// W layout (uint32 k-pair words): [layer][n(128)][kp(64)]  (k-major rows, full K)
#define WB_LAYER_W (128 * 64)                 // 8192 words per layer

// ---------------- static device scratch (no allocation allowed) ----------------
__device__ int      g_cnt_src[NN];
__device__ int      g_cnt_dst[NN];
__device__ int      g_fill[NN];
__device__ int      g_row_ptr[NN + 1];
__device__ int      g_csr_src[EE];
__device__ int      g_part[SCAN_G];
__device__ int      g_partoff[SCAN_G];
__device__ float    g_norm_src[NN];
__device__ float    g_norm_dst[NN];
__device__ uint32_t g_h_h[(NN + 128) * (DD / 2)];   // layer input h (half2), padded
__device__ uint32_t g_hs_h[NN * (DD / 2)];          // GEMM out hs (half2)
__device__ uint32_t g_w_hi[3 * WB_LAYER_W];
__device__ uint32_t g_w_lo[3 * WB_LAYER_W];

// ---------------- helpers ----------------
__device__ __forceinline__ uint32_t h2_to_u32(__half2 h) {
    uint32_t u; memcpy(&u, &h, 4); return u;
}
__device__ __forceinline__ __half2 u32_to_h2(uint32_t u) {
    __half2 h; memcpy(&h, &u, 4); return h;
}

__device__ __forceinline__ void split2(float a, float b, uint32_t& hi, uint32_t& lo) {
    __half ha = __float2half_rn(a), hb = __float2half_rn(b);
    float ra = a - __half2float(ha), rb = b - __half2float(hb);
    __half la = __float2half_rn(ra), lb = __float2half_rn(rb);
    hi = ((uint32_t)__half_as_ushort(hb) << 16) | (uint32_t)__half_as_ushort(ha);
    lo = ((uint32_t)__half_as_ushort(lb) << 16) | (uint32_t)__half_as_ushort(la);
}

__device__ __forceinline__ void mma_f16(float* c, const uint32_t* a, const uint32_t* b) {
    asm volatile(
        "mma.sync.aligned.m16n8k16.row.col.f32.f16.f16.f32 "
        "{%0,%1,%2,%3}, {%4,%5,%6,%7}, {%8,%9}, {%0,%1,%2,%3};"
        : "+f"(c[0]), "+f"(c[1]), "+f"(c[2]), "+f"(c[3])
        : "r"(a[0]), "r"(a[1]), "r"(a[2]), "r"(a[3]), "r"(b[0]), "r"(b[1]));
}

__device__ __forceinline__ void ldsm_x4(uint32_t& r0, uint32_t& r1, uint32_t& r2,
                                        uint32_t& r3, uint32_t saddr) {
    asm volatile("ldmatrix.sync.aligned.m8n8.x4.shared.b16 {%0,%1,%2,%3}, [%4];"
                 : "=r"(r0), "=r"(r1), "=r"(r2), "=r"(r3) : "r"(saddr));
}

#define CP_ASYNC16(saddr, gptr) \
    asm volatile("cp.async.cg.shared.global [%0], [%1], 16;" :: "r"(saddr), "l"(gptr))
#define CP_COMMIT() asm volatile("cp.async.commit_group;" ::: "memory")
#define CP_WAIT0()  asm volatile("cp.async.wait_group 0;" ::: "memory")

// ---------------- init: zero counters + prep all 3 W layers ----------------
__global__ void __launch_bounds__(256) k_init(const float* __restrict__ W0,
                                              const float* __restrict__ W1,
                                              const float* __restrict__ W2) {
    int i = blockIdx.x * blockDim.x + threadIdx.x;
    if (i < NN) { g_cnt_src[i] = 0; g_cnt_dst[i] = 0; g_fill[i] = 0; }
    if (i < 3 * 8192) {
        int layer = i >> 13;
        int idx = i & 8191;
        const float* W = (layer == 0) ? W0 : (layer == 1) ? W1 : W2;
        int kp = idx >> 7;       // 0..63
        int n = idx & 127;
        float w0 = W[(2 * kp) * DD + n];
        float w1 = W[(2 * kp + 1) * DD + n];
        uint32_t hi, lo;
        split2(w0, w1, hi, lo);
        int dst = layer * WB_LAYER_W + n * 64 + kp;
        g_w_hi[dst] = hi;
        g_w_lo[dst] = lo;
    }
}

// ---------------- graph preprocessing ----------------
__global__ void k_degree(const int* __restrict__ src, const int* __restrict__ dst) {
    int e = blockIdx.x * blockDim.x + threadIdx.x;
    if (e < EE) {
        atomicAdd(&g_cnt_src[src[e]], 1);
        atomicAdd(&g_cnt_dst[dst[e]], 1);
    }
}

// norms + convert x*norm_src -> fp16 into g_h_h (layer-0 GEMM input)
// one thread per half2 word: NN * 64 threads
__global__ void __launch_bounds__(256) k_norm_prep(const float* __restrict__ x) {
    int i = blockIdx.x * blockDim.x + threadIdx.x;
    if (i >= NN * 64) return;
    int row = i >> 6;
    int q = i & 63;                 // half2 word index (2 cols), 0..63
    float ns = rsqrtf((float)max(g_cnt_src[row], 1));
    if (q == 0) {
        g_norm_src[row] = ns;
        g_norm_dst[row] = rsqrtf((float)max(g_cnt_dst[row], 1));
    }
    float2 v = *(const float2*)(x + (size_t)row * DD + q * 2);
    g_h_h[(size_t)row * 64 + q] =
        h2_to_u32(__floats2half2_rn(v.x * ns, v.y * ns));
}

__global__ void __launch_bounds__(SCAN_B) k_scan_part() {
    __shared__ int s[SCAN_B];
    int t = threadIdx.x;
    int i = blockIdx.x * SCAN_B + t;
    s[t] = (i < NN) ? g_cnt_dst[i] : 0;
    __syncthreads();
    for (int off = SCAN_B / 2; off > 0; off >>= 1) {
        if (t < off) s[t] += s[t + off];
        __syncthreads();
    }
    if (t == 0) g_part[blockIdx.x] = s[0];
}

__global__ void __launch_bounds__(512) k_scan_top() {
    __shared__ int s[512];
    int t = threadIdx.x;
    int v = (t < SCAN_G) ? g_part[t] : 0;
    s[t] = v;
    __syncthreads();
    for (int off = 1; off < 512; off <<= 1) {
        int u = (t >= off) ? s[t - off] : 0;
        __syncthreads();
        s[t] += u;
        __syncthreads();
    }
    if (t < SCAN_G) g_partoff[t] = s[t] - v;
    if (t == 511) g_row_ptr[NN] = s[511];
}

__global__ void __launch_bounds__(SCAN_B) k_scan_write() {
    __shared__ int s[SCAN_B];
    int t = threadIdx.x;
    int i = blockIdx.x * SCAN_B + t;
    int v = (i < NN) ? g_cnt_dst[i] : 0;
    s[t] = v;
    __syncthreads();
    for (int off = 1; off < SCAN_B; off <<= 1) {
        int u = (t >= off) ? s[t - off] : 0;
        __syncthreads();
        s[t] += u;
        __syncthreads();
    }
    if (i < NN) g_row_ptr[i] = g_partoff[blockIdx.x] + s[t] - v;
}

__global__ void k_fill(const int* __restrict__ src, const int* __restrict__ dst) {
    int e = blockIdx.x * blockDim.x + threadIdx.x;
    if (e < EE) {
        int d = dst[e];
        int pos = g_row_ptr[d] + atomicAdd(&g_fill[d], 1);
        g_csr_src[pos] = src[e];
    }
}

// ---------------- single-stage mma.sync GEMM: g_hs_h = half2(g_h_h @ W) ----------------
// Full K staged once: A fp16 [m(128)][kp(64)] stride 68, B hi/lo [n(128)][kp(64)] stride 68.
// No mainloop barriers: one cp.async prologue, one wait, one sync, 8 straight k16 steps.
#define ROW_ST 68
#define TILE_W (128 * ROW_ST)                   // 8704 words
#define SM_A   0
#define SM_BH  TILE_W
#define SM_BL  (2 * TILE_W)
#define SM_WORDS (3 * TILE_W)                   // 26112
#define SM_BYTES (SM_WORDS * 4)                 // 104448

__global__ void __launch_bounds__(256, 2)
k_gemm_mma(int layer) {
    extern __shared__ uint32_t sm[];
    uint32_t sm_base = (uint32_t)__cvta_generic_to_shared(sm);
    int tid = threadIdx.x;
    int lane = tid & 31;
    int wid = tid >> 5;
    int row0 = blockIdx.x * 128;
    int m0 = (wid & 3) * 32;
    int n0 = (wid >> 2) * 64;
    int r = lane >> 2;
    int cq = lane & 3;
    int g4 = lane >> 3;
    int rl = lane & 7;

    const uint32_t* BHg = g_w_hi + layer * WB_LAYER_W;
    const uint32_t* BLg = g_w_lo + layer * WB_LAYER_W;

    // prologue: stage A (2048 quads) + B hi/lo (2048 quads each)
#pragma unroll
    for (int q = 0; q < 8; q++) {
        int fi = tid + q * 256;                 // 0..2047
        int row = fi >> 4;
        int q4 = fi & 15;
        uint32_t doff = (row * ROW_ST + q4 * 4) * 4;
        CP_ASYNC16(sm_base + SM_A * 4 + doff,
                   (const uint4*)(g_h_h + (size_t)(row0 + row) * 64) + q4);
        CP_ASYNC16(sm_base + SM_BH * 4 + doff, (const uint4*)BHg + fi);
        CP_ASYNC16(sm_base + SM_BL * 4 + doff, (const uint4*)BLg + fi);
    }
    CP_COMMIT();

    float acc[2][8][4];
#pragma unroll
    for (int mi = 0; mi < 2; mi++)
#pragma unroll
        for (int ni = 0; ni < 8; ni++)
#pragma unroll
            for (int q = 0; q < 4; q++) acc[mi][ni][q] = 0.f;

    CP_WAIT0();
    __syncthreads();

    const uint32_t* A0 = sm + SM_A;
    uint32_t bh_base = sm_base + SM_BH * 4;
    uint32_t bl_base = sm_base + SM_BL * 4;
#pragma unroll
    for (int ks = 0; ks < 8; ks++) {
        uint32_t ah[2][4];
#pragma unroll
        for (int mi = 0; mi < 2; mi++) {
            int b0 = (m0 + mi * 16 + r) * ROW_ST + ks * 8 + cq;
            int b1 = b0 + 8 * ROW_ST;
            ah[mi][0] = A0[b0];     ah[mi][1] = A0[b1];
            ah[mi][2] = A0[b0 + 4]; ah[mi][3] = A0[b1 + 4];
        }
#pragma unroll
        for (int ni2 = 0; ni2 < 4; ni2++) {
            int nrow = n0 + ni2 * 16 + (g4 >> 1) * 8 + rl;
            uint32_t maddr = (uint32_t)(nrow * ROW_ST) * 4 + (uint32_t)(ks * 8 + (g4 & 1) * 4) * 4;
            uint32_t bh0, bh1, bh2, bh3, bl0, bl1, bl2, bl3;
            ldsm_x4(bh0, bh1, bh2, bh3, bh_base + maddr);
            ldsm_x4(bl0, bl1, bl2, bl3, bl_base + maddr);
            uint32_t bhfA[2] = { bh0, bh1 }, blfA[2] = { bl0, bl1 };
            uint32_t bhfB[2] = { bh2, bh3 }, blfB[2] = { bl2, bl3 };
#pragma unroll
            for (int mi = 0; mi < 2; mi++) {
                mma_f16(acc[mi][ni2 * 2], ah[mi], bhfA);
                mma_f16(acc[mi][ni2 * 2], ah[mi], blfA);
                mma_f16(acc[mi][ni2 * 2 + 1], ah[mi], bhfB);
                mma_f16(acc[mi][ni2 * 2 + 1], ah[mi], blfB);
            }
        }
    }

    // epilogue: pack half2, write -> g_hs_h (row = 64 words)
#pragma unroll
    for (int mi = 0; mi < 2; mi++) {
        int rowA = row0 + m0 + mi * 16 + r;
        int rowB = rowA + 8;
#pragma unroll
        for (int ni = 0; ni < 8; ni++) {
            int wcol = (n0 + ni * 8 + cq * 2) >> 1;
            if (rowA < NN)
                g_hs_h[(size_t)rowA * 64 + wcol] =
                    h2_to_u32(__floats2half2_rn(acc[mi][ni][0], acc[mi][ni][1]));
            if (rowB < NN)
                g_hs_h[(size_t)rowB * 64 + wcol] =
                    h2_to_u32(__floats2half2_rn(acc[mi][ni][2], acc[mi][ni][3]));
        }
    }
}

// ---------------- aggregate (gather CSR, fp16 source, unroll x4) ----------------
__global__ void __launch_bounds__(256)
k_agg(float* __restrict__ outExt,
      const float* __restrict__ bias,
      const float* __restrict__ gamma, const float* __restrict__ beta,
      const float* __restrict__ mean, const float* __restrict__ var,
      int do_bn) {
    int warp = (blockIdx.x * blockDim.x + threadIdx.x) >> 5;
    int lane = threadIdx.x & 31;
    if (warp >= NN) return;

    int s0 = g_row_ptr[warp];
    int s1 = g_row_ptr[warp + 1];
    int wcol = lane * 2;
    const uint32_t* hs = g_hs_h;
    const int* csr = g_csr_src;

    float4 ac0 = make_float4(0.f, 0.f, 0.f, 0.f);
    float4 ac1 = make_float4(0.f, 0.f, 0.f, 0.f);
    float4 ac2 = make_float4(0.f, 0.f, 0.f, 0.f);
    float4 ac3 = make_float4(0.f, 0.f, 0.f, 0.f);
    int j = s0;
    for (; j + 3 < s1; j += 4) {
        int i0 = csr[j], i1 = csr[j + 1], i2 = csr[j + 2], i3 = csr[j + 3];
        uint2 v0 = *(const uint2*)(hs + (size_t)i0 * 64 + wcol);
        uint2 v1 = *(const uint2*)(hs + (size_t)i1 * 64 + wcol);
        uint2 v2 = *(const uint2*)(hs + (size_t)i2 * 64 + wcol);
        uint2 v3 = *(const uint2*)(hs + (size_t)i3 * 64 + wcol);
        float2 p, q;
        p = __half22float2(u32_to_h2(v0.x)); q = __half22float2(u32_to_h2(v0.y));
        ac0.x += p.x; ac0.y += p.y; ac0.z += q.x; ac0.w += q.y;
        p = __half22float2(u32_to_h2(v1.x)); q = __half22float2(u32_to_h2(v1.y));
        ac1.x += p.x; ac1.y += p.y; ac1.z += q.x; ac1.w += q.y;
        p = __half22float2(u32_to_h2(v2.x)); q = __half22float2(u32_to_h2(v2.y));
        ac2.x += p.x; ac2.y += p.y; ac2.z += q.x; ac2.w += q.y;
        p = __half22float2(u32_to_h2(v3.x)); q = __half22float2(u32_to_h2(v3.y));
        ac3.x += p.x; ac3.y += p.y; ac3.z += q.x; ac3.w += q.y;
    }
    for (; j < s1; j++) {
        int i0 = csr[j];
        uint2 v0 = *(const uint2*)(hs + (size_t)i0 * 64 + wcol);
        float2 p = __half22float2(u32_to_h2(v0.x));
        float2 q = __half22float2(u32_to_h2(v0.y));
        ac0.x += p.x; ac0.y += p.y; ac0.z += q.x; ac0.w += q.y;
    }
    ac0.x += ac1.x + ac2.x + ac3.x;
    ac0.y += ac1.y + ac2.y + ac3.y;
    ac0.z += ac1.z + ac2.z + ac3.z;
    ac0.w += ac1.w + ac2.w + ac3.w;

    int c = lane * 4;
    float nd = g_norm_dst[warp];
    float4 bb = *(const float4*)(bias + c);
    float4 rr;
    rr.x = ac0.x * nd + bb.x;
    rr.y = ac0.y * nd + bb.y;
    rr.z = ac0.z * nd + bb.z;
    rr.w = ac0.w * nd + bb.w;

    if (do_bn) {
        float4 g = *(const float4*)(gamma + c);
        float4 be = *(const float4*)(beta + c);
        float4 m = *(const float4*)(mean + c);
        float4 vv = *(const float4*)(var + c);
        float ns = g_norm_src[warp];
        rr.x = fmaxf((rr.x - m.x) * rsqrtf(vv.x + BN_EPS) * g.x + be.x, 0.f) * ns;
        rr.y = fmaxf((rr.y - m.y) * rsqrtf(vv.y + BN_EPS) * g.y + be.y, 0.f) * ns;
        rr.z = fmaxf((rr.z - m.z) * rsqrtf(vv.z + BN_EPS) * g.z + be.z, 0.f) * ns;
        rr.w = fmaxf((rr.w - m.w) * rsqrtf(vv.w + BN_EPS) * g.w + be.w, 0.f) * ns;
        uint2 o;
        o.x = h2_to_u32(__floats2half2_rn(rr.x, rr.y));
        o.y = h2_to_u32(__floats2half2_rn(rr.z, rr.w));
        *(uint2*)(g_h_h + (size_t)warp * 64 + wcol) = o;
    } else {
        *(float4*)(outExt + (size_t)warp * DD + c) = rr;
    }
}

// ---------------- launch ----------------
extern "C" void kernel_launch(void* const* d_in, const int* in_sizes, int n_in,
                              void* d_out, int out_size) {
    const float* x   = (const float*)d_in[0];
    const int* esrc  = (const int*)d_in[1];
    const int* edst  = (const int*)d_in[2];
    const float* W0  = (const float*)d_in[3];
    const float* b0  = (const float*)d_in[4];
    const float* W1  = (const float*)d_in[5];
    const float* b1  = (const float*)d_in[6];
    const float* W2  = (const float*)d_in[7];
    const float* b2  = (const float*)d_in[8];
    const float* g0  = (const float*)d_in[9];
    const float* be0 = (const float*)d_in[10];
    const float* m0  = (const float*)d_in[11];
    const float* v0  = (const float*)d_in[12];
    const float* g1  = (const float*)d_in[13];
    const float* be1 = (const float*)d_in[14];
    const float* m1  = (const float*)d_in[15];
    const float* v1  = (const float*)d_in[16];
    float* out = (float*)d_out;

    const int nblkN = (NN + 255) / 256;
    const int nblkE = (EE + 255) / 256;
    const int nblkNP = (NN * 64 + 255) / 256;      // norm+prep: one thread per half2 word
    const int gemmBlocks = (NN + 127) / 128;       // 782
    const int aggBlocks = (NN * 32 + 255) / 256;

    cudaFuncSetAttribute(k_gemm_mma, cudaFuncAttributeMaxDynamicSharedMemorySize, SM_BYTES);

    // launch 0: init (zero counters + prep all W)
    k_init<<<nblkN, 256>>>(W0, W1, W2);
    // launch 1: degrees
    k_degree<<<nblkE, 256>>>(esrc, edst);
    // launch 2: norms + x*norm -> fp16 g_h_h
    k_norm_prep<<<nblkNP, 256>>>(x);
    // launch 3: layer-0 GEMM  (profiled slot)
    k_gemm_mma<<<gemmBlocks, 256, SM_BYTES>>>(0);
    // launches 4-7: CSR build (independent of GEMM)
    k_scan_part<<<SCAN_G, SCAN_B>>>();
    k_scan_top<<<1, 512>>>();
    k_scan_write<<<SCAN_G, SCAN_B>>>();
    k_fill<<<nblkE, 256>>>(esrc, edst);
    // layer 0 aggregate
    k_agg<<<aggBlocks, 256>>>(nullptr, b0, g0, be0, m0, v0, 1);
    // layer 1
    k_gemm_mma<<<gemmBlocks, 256, SM_BYTES>>>(1);
    k_agg<<<aggBlocks, 256>>>(nullptr, b1, g1, be1, m1, v1, 1);
    // layer 2 -> d_out
    k_gemm_mma<<<gemmBlocks, 256, SM_BYTES>>>(2);
    k_agg<<<aggBlocks, 256>>>(out, b2, nullptr, nullptr, nullptr, nullptr, 0);
}

// round 17
// speedup vs baseline: 1.2836x; 1.0821x over previous
#include <cuda_runtime.h>
#include <cuda_fp16.h>
#include <cstdint>
#include <cstring>

#define NN 100000
#define EE 1000000
#define DD 128
#define BN_EPS 1e-5f

#define SCAN_B 256
#define SCAN_G ((NN + SCAN_B - 1) / SCAN_B)   // 391

// W layout (uint32 k-pair words): [layer][n(128)][kp(64)]  (k-major rows, full K)
#define WB_LAYER_W (128 * 64)                 // 8192 words per layer

// ---------------- static device scratch (no allocation allowed) ----------------
__device__ int      g_cnt_src[NN];
__device__ int      g_cnt_dst[NN];
__device__ int      g_fill[NN];
__device__ int      g_row_ptr[NN + 1];
__device__ int      g_csr_src[EE];
__device__ int      g_part[SCAN_G];
__device__ int      g_partoff[SCAN_G];
__device__ float    g_norm_src[NN];
__device__ float    g_norm_dst[NN];
__device__ uint32_t g_h_h[(NN + 128) * (DD / 2)];   // layer input h (half2), padded
__device__ uint32_t g_hs_h[NN * (DD / 2)];          // GEMM out hs (half2)
__device__ uint32_t g_w_hi[3 * WB_LAYER_W];
__device__ uint32_t g_w_lo[3 * WB_LAYER_W];
__device__ float    g_bn_coef[2 * DD];              // per-BN-layer affine
__device__ float    g_bn_shift[2 * DD];

// ---------------- helpers ----------------
__device__ __forceinline__ uint32_t h2_to_u32(__half2 h) {
    uint32_t u; memcpy(&u, &h, 4); return u;
}
__device__ __forceinline__ __half2 u32_to_h2(uint32_t u) {
    __half2 h; memcpy(&h, &u, 4); return h;
}

__device__ __forceinline__ void split2(float a, float b, uint32_t& hi, uint32_t& lo) {
    __half ha = __float2half_rn(a), hb = __float2half_rn(b);
    float ra = a - __half2float(ha), rb = b - __half2float(hb);
    __half la = __float2half_rn(ra), lb = __float2half_rn(rb);
    hi = ((uint32_t)__half_as_ushort(hb) << 16) | (uint32_t)__half_as_ushort(ha);
    lo = ((uint32_t)__half_as_ushort(lb) << 16) | (uint32_t)__half_as_ushort(la);
}

__device__ __forceinline__ void mma_f16(float* c, const uint32_t* a, const uint32_t* b) {
    asm volatile(
        "mma.sync.aligned.m16n8k16.row.col.f32.f16.f16.f32 "
        "{%0,%1,%2,%3}, {%4,%5,%6,%7}, {%8,%9}, {%0,%1,%2,%3};"
        : "+f"(c[0]), "+f"(c[1]), "+f"(c[2]), "+f"(c[3])
        : "r"(a[0]), "r"(a[1]), "r"(a[2]), "r"(a[3]), "r"(b[0]), "r"(b[1]));
}

__device__ __forceinline__ void ldsm_x4(uint32_t& r0, uint32_t& r1, uint32_t& r2,
                                        uint32_t& r3, uint32_t saddr) {
    asm volatile("ldmatrix.sync.aligned.m8n8.x4.shared.b16 {%0,%1,%2,%3}, [%4];"
                 : "=r"(r0), "=r"(r1), "=r"(r2), "=r"(r3) : "r"(saddr));
}

#define CP_ASYNC16(saddr, gptr) \
    asm volatile("cp.async.cg.shared.global [%0], [%1], 16;" :: "r"(saddr), "l"(gptr))
#define CP_COMMIT() asm volatile("cp.async.commit_group;" ::: "memory")
#define CP_WAIT0()  asm volatile("cp.async.wait_group 0;" ::: "memory")

// ---------------- init: zero counters + prep W layers + BN affine ----------------
__global__ void __launch_bounds__(256) k_init(const float* __restrict__ W0,
                                              const float* __restrict__ W1,
                                              const float* __restrict__ W2,
                                              const float* __restrict__ b0,
                                              const float* __restrict__ b1,
                                              const float* __restrict__ g0,
                                              const float* __restrict__ be0,
                                              const float* __restrict__ m0,
                                              const float* __restrict__ v0,
                                              const float* __restrict__ g1,
                                              const float* __restrict__ be1,
                                              const float* __restrict__ m1,
                                              const float* __restrict__ v1) {
    int i = blockIdx.x * blockDim.x + threadIdx.x;
    if (i < NN) { g_cnt_src[i] = 0; g_cnt_dst[i] = 0; g_fill[i] = 0; }
    if (i < 3 * 8192) {
        int layer = i >> 13;
        int idx = i & 8191;
        const float* W = (layer == 0) ? W0 : (layer == 1) ? W1 : W2;
        int kp = idx >> 7;       // 0..63
        int n = idx & 127;
        float w0 = W[(2 * kp) * DD + n];
        float w1 = W[(2 * kp + 1) * DD + n];
        uint32_t hi, lo;
        split2(w0, w1, hi, lo);
        int dst = layer * WB_LAYER_W + n * 64 + kp;
        g_w_hi[dst] = hi;
        g_w_lo[dst] = lo;
    }
    if (i < 2 * DD) {
        int l = i >> 7;
        int c = i & 127;
        float gg = l ? g1[c] : g0[c];
        float be = l ? be1[c] : be0[c];
        float m  = l ? m1[c] : m0[c];
        float v  = l ? v1[c] : v0[c];
        float b  = l ? b1[c] : b0[c];
        float coef = gg * rsqrtf(v + BN_EPS);
        g_bn_coef[i] = coef;
        g_bn_shift[i] = (b - m) * coef + be;
    }
}

// ---------------- graph preprocessing ----------------
__global__ void k_degree(const int* __restrict__ src, const int* __restrict__ dst) {
    int e = blockIdx.x * blockDim.x + threadIdx.x;
    if (e < EE) {
        atomicAdd(&g_cnt_src[src[e]], 1);
        atomicAdd(&g_cnt_dst[dst[e]], 1);
    }
}

// norms + convert x*norm_src -> fp16 into g_h_h. One warp per row.
__global__ void __launch_bounds__(256) k_norm_prep(const float* __restrict__ x) {
    int w = (blockIdx.x * blockDim.x + threadIdx.x) >> 5;
    int lane = threadIdx.x & 31;
    if (w >= NN) return;
    float ns = rsqrtf((float)max(g_cnt_src[w], 1));
    if (lane == 0) {
        g_norm_src[w] = ns;
        g_norm_dst[w] = rsqrtf((float)max(g_cnt_dst[w], 1));
    }
    const float2* xp = (const float2*)(x + (size_t)w * DD);
    uint32_t* hp = g_h_h + (size_t)w * 64;
    float2 v0 = xp[lane];
    float2 v1 = xp[lane + 32];
    hp[lane]      = h2_to_u32(__floats2half2_rn(v0.x * ns, v0.y * ns));
    hp[lane + 32] = h2_to_u32(__floats2half2_rn(v1.x * ns, v1.y * ns));
}

__global__ void __launch_bounds__(SCAN_B) k_scan_part() {
    __shared__ int s[SCAN_B];
    int t = threadIdx.x;
    int i = blockIdx.x * SCAN_B + t;
    s[t] = (i < NN) ? g_cnt_dst[i] : 0;
    __syncthreads();
    for (int off = SCAN_B / 2; off > 0; off >>= 1) {
        if (t < off) s[t] += s[t + off];
        __syncthreads();
    }
    if (t == 0) g_part[blockIdx.x] = s[0];
}

__global__ void __launch_bounds__(512) k_scan_top() {
    __shared__ int s[512];
    int t = threadIdx.x;
    int v = (t < SCAN_G) ? g_part[t] : 0;
    s[t] = v;
    __syncthreads();
    for (int off = 1; off < 512; off <<= 1) {
        int u = (t >= off) ? s[t - off] : 0;
        __syncthreads();
        s[t] += u;
        __syncthreads();
    }
    if (t < SCAN_G) g_partoff[t] = s[t] - v;
    if (t == 511) g_row_ptr[NN] = s[511];
}

__global__ void __launch_bounds__(SCAN_B) k_scan_write() {
    __shared__ int s[SCAN_B];
    int t = threadIdx.x;
    int i = blockIdx.x * SCAN_B + t;
    int v = (i < NN) ? g_cnt_dst[i] : 0;
    s[t] = v;
    __syncthreads();
    for (int off = 1; off < SCAN_B; off <<= 1) {
        int u = (t >= off) ? s[t - off] : 0;
        __syncthreads();
        s[t] += u;
        __syncthreads();
    }
    if (i < NN) g_row_ptr[i] = g_partoff[blockIdx.x] + s[t] - v;
}

__global__ void k_fill(const int* __restrict__ src, const int* __restrict__ dst) {
    int e = blockIdx.x * blockDim.x + threadIdx.x;
    if (e < EE) {
        int d = dst[e];
        int pos = g_row_ptr[d] + atomicAdd(&g_fill[d], 1);
        g_csr_src[pos] = src[e];
    }
}

// ---------------- single-stage mma.sync GEMM: g_hs_h = half2(g_h_h @ W) ----------------
#define ROW_ST 68
#define TILE_W (128 * ROW_ST)                   // 8704 words
#define SM_A   0
#define SM_BH  TILE_W
#define SM_BL  (2 * TILE_W)
#define SM_WORDS (3 * TILE_W)                   // 26112
#define SM_BYTES (SM_WORDS * 4)                 // 104448

__global__ void __launch_bounds__(256, 2)
k_gemm_mma(int layer) {
    extern __shared__ uint32_t sm[];
    uint32_t sm_base = (uint32_t)__cvta_generic_to_shared(sm);
    int tid = threadIdx.x;
    int lane = tid & 31;
    int wid = tid >> 5;
    int row0 = blockIdx.x * 128;
    int m0 = (wid & 3) * 32;
    int n0 = (wid >> 2) * 64;
    int r = lane >> 2;
    int cq = lane & 3;
    int g4 = lane >> 3;
    int rl = lane & 7;

    const uint32_t* BHg = g_w_hi + layer * WB_LAYER_W;
    const uint32_t* BLg = g_w_lo + layer * WB_LAYER_W;

#pragma unroll
    for (int q = 0; q < 8; q++) {
        int fi = tid + q * 256;                 // 0..2047
        int row = fi >> 4;
        int q4 = fi & 15;
        uint32_t doff = (row * ROW_ST + q4 * 4) * 4;
        CP_ASYNC16(sm_base + SM_A * 4 + doff,
                   (const uint4*)(g_h_h + (size_t)(row0 + row) * 64) + q4);
        CP_ASYNC16(sm_base + SM_BH * 4 + doff, (const uint4*)BHg + fi);
        CP_ASYNC16(sm_base + SM_BL * 4 + doff, (const uint4*)BLg + fi);
    }
    CP_COMMIT();

    float acc[2][8][4];
#pragma unroll
    for (int mi = 0; mi < 2; mi++)
#pragma unroll
        for (int ni = 0; ni < 8; ni++)
#pragma unroll
            for (int q = 0; q < 4; q++) acc[mi][ni][q] = 0.f;

    CP_WAIT0();
    __syncthreads();

    const uint32_t* A0 = sm + SM_A;
    uint32_t bh_base = sm_base + SM_BH * 4;
    uint32_t bl_base = sm_base + SM_BL * 4;
#pragma unroll
    for (int ks = 0; ks < 8; ks++) {
        uint32_t ah[2][4];
#pragma unroll
        for (int mi = 0; mi < 2; mi++) {
            int b0 = (m0 + mi * 16 + r) * ROW_ST + ks * 8 + cq;
            int b1 = b0 + 8 * ROW_ST;
            ah[mi][0] = A0[b0];     ah[mi][1] = A0[b1];
            ah[mi][2] = A0[b0 + 4]; ah[mi][3] = A0[b1 + 4];
        }
#pragma unroll
        for (int ni2 = 0; ni2 < 4; ni2++) {
            int nrow = n0 + ni2 * 16 + (g4 >> 1) * 8 + rl;
            uint32_t maddr = (uint32_t)(nrow * ROW_ST) * 4 + (uint32_t)(ks * 8 + (g4 & 1) * 4) * 4;
            uint32_t bh0, bh1, bh2, bh3, bl0, bl1, bl2, bl3;
            ldsm_x4(bh0, bh1, bh2, bh3, bh_base + maddr);
            ldsm_x4(bl0, bl1, bl2, bl3, bl_base + maddr);
            uint32_t bhfA[2] = { bh0, bh1 }, blfA[2] = { bl0, bl1 };
            uint32_t bhfB[2] = { bh2, bh3 }, blfB[2] = { bl2, bl3 };
#pragma unroll
            for (int mi = 0; mi < 2; mi++) {
                mma_f16(acc[mi][ni2 * 2], ah[mi], bhfA);
                mma_f16(acc[mi][ni2 * 2], ah[mi], blfA);
                mma_f16(acc[mi][ni2 * 2 + 1], ah[mi], bhfB);
                mma_f16(acc[mi][ni2 * 2 + 1], ah[mi], blfB);
            }
        }
    }

#pragma unroll
    for (int mi = 0; mi < 2; mi++) {
        int rowA = row0 + m0 + mi * 16 + r;
        int rowB = rowA + 8;
#pragma unroll
        for (int ni = 0; ni < 8; ni++) {
            int wcol = (n0 + ni * 8 + cq * 2) >> 1;
            if (rowA < NN)
                g_hs_h[(size_t)rowA * 64 + wcol] =
                    h2_to_u32(__floats2half2_rn(acc[mi][ni][0], acc[mi][ni][1]));
            if (rowB < NN)
                g_hs_h[(size_t)rowB * 64 + wcol] =
                    h2_to_u32(__floats2half2_rn(acc[mi][ni][2], acc[mi][ni][3]));
        }
    }
}

// ---------------- aggregate (gather CSR, fp16 source, unroll x4) ----------------
// do_bn: out = half2( max((agg*nd)*coef + shift, 0) * ns ) -> g_h_h  (bias folded in shift)
// else:  out = fp32 agg*nd + bias -> outExt
__global__ void __launch_bounds__(256)
k_agg(float* __restrict__ outExt,
      const float* __restrict__ bias,
      int bnLayer, int do_bn) {
    int warp = (blockIdx.x * blockDim.x + threadIdx.x) >> 5;
    int lane = threadIdx.x & 31;
    if (warp >= NN) return;

    int s0 = g_row_ptr[warp];
    int s1 = g_row_ptr[warp + 1];
    int wcol = lane * 2;
    const uint32_t* hs = g_hs_h;
    const int* csr = g_csr_src;

    float4 ac0 = make_float4(0.f, 0.f, 0.f, 0.f);
    float4 ac1 = make_float4(0.f, 0.f, 0.f, 0.f);
    float4 ac2 = make_float4(0.f, 0.f, 0.f, 0.f);
    float4 ac3 = make_float4(0.f, 0.f, 0.f, 0.f);
    int j = s0;
    for (; j + 3 < s1; j += 4) {
        int i0 = csr[j], i1 = csr[j + 1], i2 = csr[j + 2], i3 = csr[j + 3];
        uint2 v0 = *(const uint2*)(hs + (size_t)i0 * 64 + wcol);
        uint2 v1 = *(const uint2*)(hs + (size_t)i1 * 64 + wcol);
        uint2 v2 = *(const uint2*)(hs + (size_t)i2 * 64 + wcol);
        uint2 v3 = *(const uint2*)(hs + (size_t)i3 * 64 + wcol);
        float2 p, q;
        p = __half22float2(u32_to_h2(v0.x)); q = __half22float2(u32_to_h2(v0.y));
        ac0.x += p.x; ac0.y += p.y; ac0.z += q.x; ac0.w += q.y;
        p = __half22float2(u32_to_h2(v1.x)); q = __half22float2(u32_to_h2(v1.y));
        ac1.x += p.x; ac1.y += p.y; ac1.z += q.x; ac1.w += q.y;
        p = __half22float2(u32_to_h2(v2.x)); q = __half22float2(u32_to_h2(v2.y));
        ac2.x += p.x; ac2.y += p.y; ac2.z += q.x; ac2.w += q.y;
        p = __half22float2(u32_to_h2(v3.x)); q = __half22float2(u32_to_h2(v3.y));
        ac3.x += p.x; ac3.y += p.y; ac3.z += q.x; ac3.w += q.y;
    }
    for (; j < s1; j++) {
        int i0 = csr[j];
        uint2 v0 = *(const uint2*)(hs + (size_t)i0 * 64 + wcol);
        float2 p = __half22float2(u32_to_h2(v0.x));
        float2 q = __half22float2(u32_to_h2(v0.y));
        ac0.x += p.x; ac0.y += p.y; ac0.z += q.x; ac0.w += q.y;
    }
    ac0.x += ac1.x + ac2.x + ac3.x;
    ac0.y += ac1.y + ac2.y + ac3.y;
    ac0.z += ac1.z + ac2.z + ac3.z;
    ac0.w += ac1.w + ac2.w + ac3.w;

    int c = lane * 4;
    float nd = g_norm_dst[warp];

    if (do_bn) {
        float4 co = *(const float4*)(g_bn_coef + bnLayer * DD + c);
        float4 sh = *(const float4*)(g_bn_shift + bnLayer * DD + c);
        float ns = g_norm_src[warp];
        float4 rr;
        rr.x = fmaxf((ac0.x * nd) * co.x + sh.x, 0.f) * ns;
        rr.y = fmaxf((ac0.y * nd) * co.y + sh.y, 0.f) * ns;
        rr.z = fmaxf((ac0.z * nd) * co.z + sh.z, 0.f) * ns;
        rr.w = fmaxf((ac0.w * nd) * co.w + sh.w, 0.f) * ns;
        uint2 o;
        o.x = h2_to_u32(__floats2half2_rn(rr.x, rr.y));
        o.y = h2_to_u32(__floats2half2_rn(rr.z, rr.w));
        *(uint2*)(g_h_h + (size_t)warp * 64 + wcol) = o;
    } else {
        float4 bb = *(const float4*)(bias + c);
        float4 rr;
        rr.x = ac0.x * nd + bb.x;
        rr.y = ac0.y * nd + bb.y;
        rr.z = ac0.z * nd + bb.z;
        rr.w = ac0.w * nd + bb.w;
        *(float4*)(outExt + (size_t)warp * DD + c) = rr;
    }
}

// ---------------- launch ----------------
extern "C" void kernel_launch(void* const* d_in, const int* in_sizes, int n_in,
                              void* d_out, int out_size) {
    const float* x   = (const float*)d_in[0];
    const int* esrc  = (const int*)d_in[1];
    const int* edst  = (const int*)d_in[2];
    const float* W0  = (const float*)d_in[3];
    const float* b0  = (const float*)d_in[4];
    const float* W1  = (const float*)d_in[5];
    const float* b1  = (const float*)d_in[6];
    const float* W2  = (const float*)d_in[7];
    const float* b2  = (const float*)d_in[8];
    const float* g0  = (const float*)d_in[9];
    const float* be0 = (const float*)d_in[10];
    const float* m0  = (const float*)d_in[11];
    const float* v0  = (const float*)d_in[12];
    const float* g1  = (const float*)d_in[13];
    const float* be1 = (const float*)d_in[14];
    const float* m1  = (const float*)d_in[15];
    const float* v1  = (const float*)d_in[16];
    float* out = (float*)d_out;

    const int nblkN = (NN + 255) / 256;
    const int nblkE = (EE + 255) / 256;
    const int nblkNP = (NN * 32 + 255) / 256;      // warp per row
    const int gemmBlocks = (NN + 127) / 128;       // 782
    const int aggBlocks = (NN * 32 + 255) / 256;

    cudaFuncSetAttribute(k_gemm_mma, cudaFuncAttributeMaxDynamicSharedMemorySize, SM_BYTES);

    // fork-join: CSR build on a side stream overlapping norm_prep + gemm0
    cudaStream_t s2;
    cudaStreamCreate(&s2);
    cudaEvent_t evA, evB;
    cudaEventCreateWithFlags(&evA, cudaEventDisableTiming);
    cudaEventCreateWithFlags(&evB, cudaEventDisableTiming);

    // stream 0: init(0), degree(1), norm_prep(2), gemm0(3 = profiled slot)
    k_init<<<nblkN, 256>>>(W0, W1, W2, b0, b1, g0, be0, m0, v0, g1, be1, m1, v1);
    k_degree<<<nblkE, 256>>>(esrc, edst);
    cudaEventRecord(evA, 0);
    k_norm_prep<<<nblkNP, 256>>>(x);
    k_gemm_mma<<<gemmBlocks, 256, SM_BYTES>>>(0);

    // side stream: CSR build (depends only on degree)
    cudaStreamWaitEvent(s2, evA, 0);
    k_scan_part<<<SCAN_G, SCAN_B, 0, s2>>>();
    k_scan_top<<<1, 512, 0, s2>>>();
    k_scan_write<<<SCAN_G, SCAN_B, 0, s2>>>();
    k_fill<<<nblkE, 256, 0, s2>>>(esrc, edst);
    cudaEventRecord(evB, s2);

    // join, then layer pipeline
    cudaStreamWaitEvent(0, evB, 0);
    k_agg<<<aggBlocks, 256>>>(nullptr, nullptr, 0, 1);
    k_gemm_mma<<<gemmBlocks, 256, SM_BYTES>>>(1);
    k_agg<<<aggBlocks, 256>>>(nullptr, nullptr, 1, 1);
    k_gemm_mma<<<gemmBlocks, 256, SM_BYTES>>>(2);
    k_agg<<<aggBlocks, 256>>>(out, b2, 0, 0);
}